// round 6
// baseline (speedup 1.0000x reference)
#include <cuda_runtime.h>
#include <math.h>

#define NROWS 65536
#define DDIM  1024
#define SDIM  512
#define KSLOTS 64

// ---------------- scratch (device globals; no allocation allowed) ------------
__device__ float g_NS0[NROWS * SDIM];   // Q -> read -> a (reused)
__device__ float g_E[NROWS * SDIM];     // erase_vec
__device__ float g_C[NROWS * SDIM];     // content
__device__ float g_T[NROWS * DDIM];     // x + read_out (pre-LN)
__device__ float g_attn[NROWS * KSLOTS];// attn -> weighted (reused)
__device__ float g_gate[NROWS];         // write gate
__device__ float g_Kp[KSLOTS * SDIM];
__device__ float g_V[KSLOTS * SDIM];
__device__ float g_agg[2 * KSLOTS * SDIM]; // erase_agg, write_agg

// ---------------- generic 128x128x8 SGEMM, A[M,K] row-major @ B[K,N] ---------
// OP: 0=none, 1=C=acc+X (X same layout as C), 2=sigmoid(acc+bias[col]),
//     3=tanh(acc+bias[col])
template<int OP>
__global__ __launch_bounds__(256, 2)
void sgemm128(const float* __restrict__ A, int lda,
              const float* __restrict__ B, int ldb,
              float* __restrict__ C, int ldc,
              int Kdim,
              const float* __restrict__ X,
              const float* __restrict__ bias)
{
    __shared__ float As[2][8][128];
    __shared__ float Bs[2][8][128];
    const int tid = threadIdx.x;
    const int bx = blockIdx.x, by = blockIdx.y;
    const int tr = (tid >> 4) << 3;   // row offset in tile (0..120)
    const int tc = (tid & 15) << 3;   // col offset in tile

    const int aRow = tid >> 1;            // 0..127
    const int aCol = (tid & 1) << 2;      // 0 or 4
    const int bRow = tid >> 5;            // 0..7
    const int bCol = (tid & 31) << 2;     // 0..124

    const float* Aptr = A + (size_t)(by * 128 + aRow) * lda + aCol;
    const float* Bptr = B + (size_t)bRow * ldb + bx * 128 + bCol;

    float acc[8][8];
    #pragma unroll
    for (int i = 0; i < 8; ++i)
        #pragma unroll
        for (int j = 0; j < 8; ++j) acc[i][j] = 0.f;

    float4 av = *(const float4*)Aptr;
    float4 bv = *(const float4*)Bptr;
    As[0][aCol + 0][aRow] = av.x; As[0][aCol + 1][aRow] = av.y;
    As[0][aCol + 2][aRow] = av.z; As[0][aCol + 3][aRow] = av.w;
    *(float4*)&Bs[0][bRow][bCol] = bv;
    __syncthreads();

    const int KT = Kdim >> 3;
    int buf = 0;
    for (int kt = 0; kt < KT; ++kt) {
        if (kt + 1 < KT) {
            av = *(const float4*)(Aptr + (kt + 1) * 8);
            bv = *(const float4*)(Bptr + (size_t)(kt + 1) * 8 * ldb);
        }
        #pragma unroll
        for (int kk = 0; kk < 8; ++kk) {
            float a0[8], b0[8];
            *(float4*)&a0[0] = *(const float4*)&As[buf][kk][tr];
            *(float4*)&a0[4] = *(const float4*)&As[buf][kk][tr + 4];
            *(float4*)&b0[0] = *(const float4*)&Bs[buf][kk][tc];
            *(float4*)&b0[4] = *(const float4*)&Bs[buf][kk][tc + 4];
            #pragma unroll
            for (int i = 0; i < 8; ++i)
                #pragma unroll
                for (int j = 0; j < 8; ++j)
                    acc[i][j] += a0[i] * b0[j];
        }
        if (kt + 1 < KT) {
            buf ^= 1;
            As[buf][aCol + 0][aRow] = av.x; As[buf][aCol + 1][aRow] = av.y;
            As[buf][aCol + 2][aRow] = av.z; As[buf][aCol + 3][aRow] = av.w;
            *(float4*)&Bs[buf][bRow][bCol] = bv;
            __syncthreads();
        }
    }

    const int row0 = by * 128 + tr;
    const int col0 = bx * 128 + tc;
    float bvals[8];
    if (OP == 2 || OP == 3) {
        #pragma unroll
        for (int j = 0; j < 8; ++j) bvals[j] = bias[col0 + j];
    }
    #pragma unroll
    for (int i = 0; i < 8; ++i) {
        size_t off = (size_t)(row0 + i) * ldc + col0;
        float out[8];
        #pragma unroll
        for (int j = 0; j < 8; ++j) {
            float v = acc[i][j];
            if (OP == 1) v += X[off + j];
            if (OP == 2) v = 1.f / (1.f + expf(-(v + bvals[j])));
            if (OP == 3) v = tanhf(v + bvals[j]);
            out[j] = v;
        }
        *(float4*)&C[off]     = *(float4*)&out[0];
        *(float4*)&C[off + 4] = *(float4*)&out[4];
    }
}

// ---------------- state projections: Kp = state@Wk, V = state@Wv -------------
__global__ __launch_bounds__(256)
void state_proj_kernel(const float* __restrict__ state,
                       const float* __restrict__ Wk,
                       const float* __restrict__ Wv,
                       float* __restrict__ Kp, float* __restrict__ V)
{
    const float* B = (blockIdx.y == 0) ? Wk : Wv;
    float* C = (blockIdx.y == 0) ? Kp : V;
    const int bx = blockIdx.x;            // 8 col tiles of 64
    __shared__ float As[16][64];
    __shared__ float Bs[16][64];
    const int tid = threadIdx.x;
    const int rb = (tid >> 4) << 2;
    const int cb = (tid & 15) << 2;
    float acc[4][4];
    #pragma unroll
    for (int i = 0; i < 4; ++i)
        #pragma unroll
        for (int j = 0; j < 4; ++j) acc[i][j] = 0.f;

    for (int kt = 0; kt < 32; ++kt) {
        const int k0 = kt * 16;
        {
            int r = tid >> 2, c4 = (tid & 3) << 2;
            float4 v = *(const float4*)&state[r * 512 + k0 + c4];
            As[c4 + 0][r] = v.x; As[c4 + 1][r] = v.y;
            As[c4 + 2][r] = v.z; As[c4 + 3][r] = v.w;
        }
        {
            int r = tid >> 4, c4 = (tid & 15) << 2;
            *(float4*)&Bs[r][c4] = *(const float4*)&B[(k0 + r) * 512 + bx * 64 + c4];
        }
        __syncthreads();
        #pragma unroll
        for (int kk = 0; kk < 16; ++kk) {
            float a[4], b[4];
            *(float4*)a = *(const float4*)&As[kk][rb];
            *(float4*)b = *(const float4*)&Bs[kk][cb];
            #pragma unroll
            for (int i = 0; i < 4; ++i)
                #pragma unroll
                for (int j = 0; j < 4; ++j) acc[i][j] += a[i] * b[j];
        }
        __syncthreads();
    }
    #pragma unroll
    for (int i = 0; i < 4; ++i)
        *(float4*)&C[(rb + i) * 512 + bx * 64 + cb] = *(float4*)&acc[i][0];
}

// ---------------- fused logits GEMM (M x 64, K=512) + row softmax ------------
// out[n,k] = gate[n] * softmax_k( scale * sum_s A[n,s]*Bk[k,s] )
__global__ __launch_bounds__(256)
void attn_kernel(const float* __restrict__ A, int lda,
                 const float* __restrict__ Bk,   // [64,512]
                 float* __restrict__ out,        // [N,64]
                 float scale,
                 const float* __restrict__ gate) // nullable
{
    __shared__ float As[16][128];
    __shared__ float Bs[16][64];
    __shared__ float L[128][65];
    __shared__ float rmax[128], rfac[128];
    const int tid = threadIdx.x;
    const int row0 = blockIdx.x * 128;
    const int rb = (tid >> 4) << 3;
    const int cb = (tid & 15) << 2;
    float acc[8][4];
    #pragma unroll
    for (int i = 0; i < 8; ++i)
        #pragma unroll
        for (int j = 0; j < 4; ++j) acc[i][j] = 0.f;

    for (int kt = 0; kt < 32; ++kt) {
        const int k0 = kt * 16;
        #pragma unroll
        for (int j = 0; j < 2; ++j) {
            int f = tid + j * 256;
            int r = f >> 2, c4 = (f & 3) << 2;
            float4 v = *(const float4*)&A[(size_t)(row0 + r) * lda + k0 + c4];
            As[c4 + 0][r] = v.x; As[c4 + 1][r] = v.y;
            As[c4 + 2][r] = v.z; As[c4 + 3][r] = v.w;
        }
        {
            int r = tid >> 2, c4 = (tid & 3) << 2;
            float4 v = *(const float4*)&Bk[r * 512 + k0 + c4];
            Bs[c4 + 0][r] = v.x; Bs[c4 + 1][r] = v.y;
            Bs[c4 + 2][r] = v.z; Bs[c4 + 3][r] = v.w;
        }
        __syncthreads();
        #pragma unroll
        for (int kk = 0; kk < 16; ++kk) {
            float a[8], b[4];
            *(float4*)&a[0] = *(const float4*)&As[kk][rb];
            *(float4*)&a[4] = *(const float4*)&As[kk][rb + 4];
            *(float4*)&b[0] = *(const float4*)&Bs[kk][cb];
            #pragma unroll
            for (int i = 0; i < 8; ++i)
                #pragma unroll
                for (int j = 0; j < 4; ++j) acc[i][j] += a[i] * b[j];
        }
        __syncthreads();
    }
    #pragma unroll
    for (int i = 0; i < 8; ++i)
        #pragma unroll
        for (int j = 0; j < 4; ++j) L[rb + i][cb + j] = acc[i][j] * scale;
    __syncthreads();
    if (tid < 128) {
        float m = -1e30f;
        for (int c = 0; c < 64; ++c) m = fmaxf(m, L[tid][c]);
        float s = 0.f;
        for (int c = 0; c < 64; ++c) s += expf(L[tid][c] - m);
        rmax[tid] = m;
        float g = gate ? gate[row0 + tid] : 1.f;
        rfac[tid] = g / s;
    }
    __syncthreads();
    #pragma unroll
    for (int t2 = 0; t2 < 32; ++t2) {
        int e = tid + t2 * 256;
        int r = e >> 6, c = e & 63;
        out[(size_t)(row0 + r) * 64 + c] = expf(L[r][c] - rmax[r]) * rfac[r];
    }
}

// ---------------- layernorm (row 1024) fused with write-gate dot -------------
__global__ __launch_bounds__(256)
void ln_gate_kernel(const float* __restrict__ T,
                    const float* __restrict__ gamma,
                    const float* __restrict__ beta,
                    const float* __restrict__ Wg,
                    const float* __restrict__ bgp,
                    float* __restrict__ H,
                    float* __restrict__ gate)
{
    __shared__ float sm[8], sm2[8];
    __shared__ float s_mu, s_inv;
    const int row = blockIdx.x;
    const int t = threadIdx.x;
    const size_t base = (size_t)row * 1024 + t * 4;
    float4 v = *(const float4*)&T[base];
    float s  = v.x + v.y + v.z + v.w;
    float sq = v.x * v.x + v.y * v.y + v.z * v.z + v.w * v.w;
    #pragma unroll
    for (int o = 16; o > 0; o >>= 1) {
        s  += __shfl_down_sync(0xffffffffu, s, o);
        sq += __shfl_down_sync(0xffffffffu, sq, o);
    }
    const int lane = t & 31, w = t >> 5;
    if (lane == 0) { sm[w] = s; sm2[w] = sq; }
    __syncthreads();
    if (t == 0) {
        float S = 0.f, Q = 0.f;
        #pragma unroll
        for (int i = 0; i < 8; ++i) { S += sm[i]; Q += sm2[i]; }
        float mu = S * (1.f / 1024.f);
        float var = Q * (1.f / 1024.f) - mu * mu;
        s_mu = mu; s_inv = rsqrtf(var + 1e-6f);
    }
    __syncthreads();
    const float mu = s_mu, inv = s_inv;
    float4 g4 = *(const float4*)&gamma[t * 4];
    float4 b4 = *(const float4*)&beta[t * 4];
    float4 h;
    h.x = (v.x - mu) * inv * g4.x + b4.x;
    h.y = (v.y - mu) * inv * g4.y + b4.y;
    h.z = (v.z - mu) * inv * g4.z + b4.z;
    h.w = (v.w - mu) * inv * g4.w + b4.w;
    *(float4*)&H[base] = h;
    float4 wg = *(const float4*)&Wg[t * 4];
    float gd = h.x * wg.x + h.y * wg.y + h.z * wg.z + h.w * wg.w;
    #pragma unroll
    for (int o = 16; o > 0; o >>= 1) gd += __shfl_down_sync(0xffffffffu, gd, o);
    __syncthreads();
    if (lane == 0) sm[w] = gd;
    __syncthreads();
    if (t == 0) {
        float G = 0.f;
        #pragma unroll
        for (int i = 0; i < 8; ++i) G += sm[i];
        gate[row] = 1.f / (1.f + expf(-(G + bgp[0])));
    }
}

// ---------------- split-K aggregation: agg[64,512] += W^T chunk @ E chunk ----
__global__ __launch_bounds__(256)
void agg_kernel(const float* __restrict__ Wt,  // weighted [N,64]
                const float* __restrict__ E,   // [N,512]
                float* __restrict__ agg)       // [64,512]
{
    const int sTile = blockIdx.x;              // 0..3 (128 cols each)
    const int r0 = blockIdx.y * 2048;
    __shared__ float Ws[16][64];
    __shared__ float Es[16][128];
    const int tid = threadIdx.x;
    const int slot0 = (tid >> 5) << 3;         // 0..56
    const int col0  = (tid & 31) << 2;         // 0..124
    float acc[8][4];
    #pragma unroll
    for (int i = 0; i < 8; ++i)
        #pragma unroll
        for (int j = 0; j < 4; ++j) acc[i][j] = 0.f;

    for (int kt = 0; kt < 128; ++kt) {
        const int rr = r0 + kt * 16;
        {
            int r = tid >> 4, c4 = (tid & 15) << 2;
            *(float4*)&Ws[r][c4] = *(const float4*)&Wt[(size_t)(rr + r) * 64 + c4];
        }
        #pragma unroll
        for (int j = 0; j < 2; ++j) {
            int f = tid + j * 256;
            int r = f >> 5, c4 = (f & 31) << 2;
            *(float4*)&Es[r][c4] =
                *(const float4*)&E[(size_t)(rr + r) * 512 + sTile * 128 + c4];
        }
        __syncthreads();
        #pragma unroll
        for (int kk = 0; kk < 16; ++kk) {
            float w[8], e[4];
            *(float4*)&w[0] = *(const float4*)&Ws[kk][slot0];
            *(float4*)&w[4] = *(const float4*)&Ws[kk][slot0 + 4];
            *(float4*)&e[0] = *(const float4*)&Es[kk][col0];
            #pragma unroll
            for (int i = 0; i < 8; ++i)
                #pragma unroll
                for (int j = 0; j < 4; ++j) acc[i][j] += w[i] * e[j];
        }
        __syncthreads();
    }
    #pragma unroll
    for (int i = 0; i < 8; ++i)
        #pragma unroll
        for (int j = 0; j < 4; ++j)
            atomicAdd(&agg[(slot0 + i) * 512 + sTile * 128 + col0 + j], acc[i][j]);
}

__global__ void zero_kernel(float* p, int n) {
    int i = blockIdx.x * blockDim.x + threadIdx.x;
    if (i < n) p[i] = 0.f;
}

__global__ void final_state_kernel(const float* __restrict__ state,
                                   const float* __restrict__ er,
                                   const float* __restrict__ wr,
                                   float* __restrict__ out)
{
    int i = blockIdx.x * blockDim.x + threadIdx.x;   // 32768
    float e = fminf(fmaxf(er[i], 0.f), 1.f);
    out[i] = state[i] * (1.f - e) + wr[i];
}

// ------------------------------- launch --------------------------------------
extern "C" void kernel_launch(void* const* d_in, const int* in_sizes, int n_in,
                              void* d_out, int out_size)
{
    const float* X     = (const float*)d_in[0];
    const float* state = (const float*)d_in[1];
    const float* Wq    = (const float*)d_in[2];
    const float* Wk    = (const float*)d_in[3];
    const float* Wv    = (const float*)d_in[4];
    const float* Wo    = (const float*)d_in[5];
    const float* gamma = (const float*)d_in[6];
    const float* beta  = (const float*)d_in[7];
    const float* Wa    = (const float*)d_in[8];
    const float* Wg    = (const float*)d_in[9];
    const float* bg    = (const float*)d_in[10];
    const float* We    = (const float*)d_in[11];
    const float* be    = (const float*)d_in[12];
    const float* Wc    = (const float*)d_in[13];
    const float* bc    = (const float*)d_in[14];
    float* out = (float*)d_out;

    float *pNS0, *pE, *pC, *pT, *pAttn, *pGate, *pKp, *pV, *pAgg;
    cudaGetSymbolAddress((void**)&pNS0, g_NS0);
    cudaGetSymbolAddress((void**)&pE, g_E);
    cudaGetSymbolAddress((void**)&pC, g_C);
    cudaGetSymbolAddress((void**)&pT, g_T);
    cudaGetSymbolAddress((void**)&pAttn, g_attn);
    cudaGetSymbolAddress((void**)&pGate, g_gate);
    cudaGetSymbolAddress((void**)&pKp, g_Kp);
    cudaGetSymbolAddress((void**)&pV, g_V);
    cudaGetSymbolAddress((void**)&pAgg, g_agg);
    float* pAgg0 = pAgg;
    float* pAgg1 = pAgg + KSLOTS * SDIM;

    const float scale = 1.0f / sqrtf((float)SDIM);

    // zero aggregation buffers (re-done every call -> deterministic)
    zero_kernel<<<128, 512>>>(pAgg, 2 * KSLOTS * SDIM);

    // Kp = state@Wk, V = state@Wv
    state_proj_kernel<<<dim3(8, 2), 256>>>(state, Wk, Wv, pKp, pV);

    // Q = X @ Wq  -> g_NS0
    sgemm128<0><<<dim3(4, 512), 256>>>(X, DDIM, Wq, SDIM, pNS0, SDIM, DDIM,
                                       nullptr, nullptr);
    // attn = softmax(Q @ Kp^T * scale) -> g_attn
    attn_kernel<<<512, 256>>>(pNS0, SDIM, pKp, pAttn, scale, nullptr);

    // read = attn @ V -> g_NS0 (Q dead)
    sgemm128<0><<<dim3(4, 512), 256>>>(pAttn, KSLOTS, pV, SDIM, pNS0, SDIM,
                                       KSLOTS, nullptr, nullptr);
    // t = X + read @ Wo -> g_T
    sgemm128<1><<<dim3(8, 512), 256>>>(pNS0, SDIM, Wo, DDIM, pT, DDIM, SDIM,
                                       X, nullptr);
    // h = LN(t) -> d_out[0 : N*D]; gate = sigmoid(h.Wg + bg)
    ln_gate_kernel<<<NROWS, 256>>>(pT, gamma, beta, Wg, bg, out, pGate);

    // a = h @ Wa -> g_NS0 (read dead)
    sgemm128<0><<<dim3(4, 512), 256>>>(out, DDIM, Wa, SDIM, pNS0, SDIM, DDIM,
                                       nullptr, nullptr);
    // e = sigmoid(h @ We + be) -> g_E
    sgemm128<2><<<dim3(4, 512), 256>>>(out, DDIM, We, SDIM, pE, SDIM, DDIM,
                                       nullptr, be);
    // c = tanh(h @ Wc + bc) -> g_C
    sgemm128<3><<<dim3(4, 512), 256>>>(out, DDIM, Wc, SDIM, pC, SDIM, DDIM,
                                       nullptr, bc);

    // weighted = gate * softmax(a @ state^T) -> g_attn (attn dead)
    attn_kernel<<<512, 256>>>(pNS0, SDIM, state, pAttn, 1.0f, pGate);

    // erase_agg = weighted^T @ e ; write_agg = weighted^T @ c
    agg_kernel<<<dim3(4, 32), 256>>>(pAttn, pE, pAgg0);
    agg_kernel<<<dim3(4, 32), 256>>>(pAttn, pC, pAgg1);

    // new_state -> d_out[N*D : ]
    final_state_kernel<<<64, 512>>>(state, pAgg0, pAgg1,
                                    out + (size_t)NROWS * DDIM);
}

// round 9
// speedup vs baseline: 3.4897x; 3.4897x over previous
#include <cuda_runtime.h>
#include <math.h>
#include <stdint.h>

#define NROWS 65536
#define DDIM  1024
#define SDIM  512
#define KSLOTS 64

// ---------------- scratch (device globals; no allocation allowed) ------------
__device__ float g_E[NROWS * SDIM];       // erase_vec
__device__ float g_C[NROWS * SDIM];       // content
__device__ float g_T[NROWS * DDIM];       // x + read_out (pre-LN)
__device__ float g_attn[NROWS * KSLOTS];  // attn -> weighted (reused)
__device__ float g_gate[NROWS];           // write gate
__device__ float g_Kp[KSLOTS * SDIM];
__device__ float g_V[KSLOTS * SDIM];
__device__ float g_M1[DDIM * KSLOTS];     // Wq @ Kp^T
__device__ float g_M2[DDIM * KSLOTS];     // Wa @ state^T
__device__ float g_VWo[KSLOTS * DDIM];    // V @ Wo
__device__ float g_agg[2 * KSLOTS * SDIM];

// ================= tf32 tensor-core GEMM: C = act(A[M,1024]@B[1024,512]+bias)
__device__ __forceinline__ uint32_t f2tf(float x) {
    uint32_t t; asm("cvt.rna.tf32.f32 %0, %1;" : "=r"(t) : "f"(x)); return t;
}
__device__ __forceinline__ void st4tf(uint32_t* p, float4 v) {
    p[0] = f2tf(v.x); p[1] = f2tf(v.y); p[2] = f2tf(v.z); p[3] = f2tf(v.w);
}
__device__ __forceinline__ void mma_tf32(float* d, const uint32_t* a,
                                         const uint32_t* b) {
    asm volatile(
        "mma.sync.aligned.m16n8k8.row.col.f32.tf32.tf32.f32 "
        "{%0,%1,%2,%3}, {%4,%5,%6,%7}, {%8,%9}, {%0,%1,%2,%3};\n"
        : "+f"(d[0]), "+f"(d[1]), "+f"(d[2]), "+f"(d[3])
        : "r"(a[0]), "r"(a[1]), "r"(a[2]), "r"(a[3]), "r"(b[0]), "r"(b[1]));
}

template<int OP>  // 2 = sigmoid(acc+bias), 3 = tanh(acc+bias)
__global__ __launch_bounds__(256)
void tf32gemm(const float* __restrict__ A,   // [M,1024] row-major
              const float* __restrict__ B,   // [1024,512] row-major
              float* __restrict__ C,         // [M,512]
              const float* __restrict__ bias)// [512]
{
    __shared__ uint32_t As[2][128][20];   // [m][k], pad 20 -> conflict-free frags
    __shared__ uint32_t Bs[2][16][136];   // [k][n], pad 136
    const int tid = threadIdx.x;
    const int bx = blockIdx.x, by = blockIdx.y;
    const int lane = tid & 31;
    const int w = tid >> 5;
    const int wm = w & 1, wn = w >> 1;            // warp grid 2(M) x 4(N)
    const int g = lane >> 2, cc = lane & 3;

    const int ar = tid >> 2, ac = (tid & 3) << 2; // A tile: 128 rows x 16 k
    const int br = tid >> 5, bc = (tid & 31) << 2;// B tile: 16 k x 128 n

    const float* Ag = A + (size_t)(by * 128 + ar) * 1024 + ac;
    const float* Bg = B + (size_t)br * 512 + bx * 128 + bc;

    float acc[4][4][4];
    #pragma unroll
    for (int i = 0; i < 4; ++i)
        #pragma unroll
        for (int j = 0; j < 4; ++j)
            #pragma unroll
            for (int r = 0; r < 4; ++r) acc[i][j][r] = 0.f;

    float4 a0v = *(const float4*)Ag;
    float4 a1v = *(const float4*)(Ag + (size_t)64 * 1024);
    float4 b0v = *(const float4*)Bg;
    float4 b1v = *(const float4*)(Bg + (size_t)8 * 512);
    st4tf(&As[0][ar][ac], a0v);
    st4tf(&As[0][ar + 64][ac], a1v);
    st4tf(&Bs[0][br][bc], b0v);
    st4tf(&Bs[0][br + 8][bc], b1v);
    __syncthreads();

    int buf = 0;
    for (int kt = 0; kt < 64; ++kt) {
        if (kt < 63) {
            a0v = *(const float4*)(Ag + (kt + 1) * 16);
            a1v = *(const float4*)(Ag + (kt + 1) * 16 + (size_t)64 * 1024);
            b0v = *(const float4*)(Bg + (size_t)(kt + 1) * 16 * 512);
            b1v = *(const float4*)(Bg + (size_t)((kt + 1) * 16 + 8) * 512);
        }
        #pragma unroll
        for (int s = 0; s < 2; ++s) {
            const int kk = s * 8;
            uint32_t af[4][4], bf[4][2];
            #pragma unroll
            for (int i = 0; i < 4; ++i) {
                const int m = wm * 64 + i * 16 + g;
                af[i][0] = As[buf][m][kk + cc];
                af[i][1] = As[buf][m + 8][kk + cc];
                af[i][2] = As[buf][m][kk + cc + 4];
                af[i][3] = As[buf][m + 8][kk + cc + 4];
            }
            #pragma unroll
            for (int j = 0; j < 4; ++j) {
                const int n = wn * 32 + j * 8 + g;
                bf[j][0] = Bs[buf][kk + cc][n];
                bf[j][1] = Bs[buf][kk + cc + 4][n];
            }
            #pragma unroll
            for (int i = 0; i < 4; ++i)
                #pragma unroll
                for (int j = 0; j < 4; ++j)
                    mma_tf32(acc[i][j], af[i], bf[j]);
        }
        if (kt < 63) {
            buf ^= 1;
            st4tf(&As[buf][ar][ac], a0v);
            st4tf(&As[buf][ar + 64][ac], a1v);
            st4tf(&Bs[buf][br][bc], b0v);
            st4tf(&Bs[buf][br + 8][bc], b1v);
            __syncthreads();
        }
    }

    #pragma unroll
    for (int i = 0; i < 4; ++i) {
        const int row = by * 128 + wm * 64 + i * 16 + g;
        #pragma unroll
        for (int j = 0; j < 4; ++j) {
            const int col = bx * 128 + wn * 32 + j * 8 + 2 * cc;
            const float bb0 = bias[col], bb1 = bias[col + 1];
            float v0 = acc[i][j][0] + bb0, v1 = acc[i][j][1] + bb1;
            float v2 = acc[i][j][2] + bb0, v3 = acc[i][j][3] + bb1;
            if (OP == 2) {
                v0 = 1.f / (1.f + expf(-v0)); v1 = 1.f / (1.f + expf(-v1));
                v2 = 1.f / (1.f + expf(-v2)); v3 = 1.f / (1.f + expf(-v3));
            } else {
                v0 = tanhf(v0); v1 = tanhf(v1);
                v2 = tanhf(v2); v3 = tanhf(v3);
            }
            float2 p0; p0.x = v0; p0.y = v1;
            float2 p1; p1.x = v2; p1.y = v3;
            *(float2*)&C[(size_t)row * 512 + col] = p0;
            *(float2*)&C[(size_t)(row + 8) * 512 + col] = p1;
        }
    }
}

// ---------------- generic 128x128x8 SGEMM (kept for K=64 read GEMM) ----------
// OP: 1 = C = acc + X
template<int OP>
__global__ __launch_bounds__(256, 2)
void sgemm128(const float* __restrict__ A, int lda,
              const float* __restrict__ B, int ldb,
              float* __restrict__ C, int ldc,
              int Kdim,
              const float* __restrict__ X)
{
    __shared__ float As[2][8][128];
    __shared__ float Bs[2][8][128];
    const int tid = threadIdx.x;
    const int bx = blockIdx.x, by = blockIdx.y;
    const int tr = (tid >> 4) << 3;
    const int tc = (tid & 15) << 3;

    const int aRow = tid >> 1;
    const int aCol = (tid & 1) << 2;
    const int bRow = tid >> 5;
    const int bCol = (tid & 31) << 2;

    const float* Aptr = A + (size_t)(by * 128 + aRow) * lda + aCol;
    const float* Bptr = B + (size_t)bRow * ldb + bx * 128 + bCol;

    float acc[8][8];
    #pragma unroll
    for (int i = 0; i < 8; ++i)
        #pragma unroll
        for (int j = 0; j < 8; ++j) acc[i][j] = 0.f;

    float4 av = *(const float4*)Aptr;
    float4 bv = *(const float4*)Bptr;
    As[0][aCol + 0][aRow] = av.x; As[0][aCol + 1][aRow] = av.y;
    As[0][aCol + 2][aRow] = av.z; As[0][aCol + 3][aRow] = av.w;
    *(float4*)&Bs[0][bRow][bCol] = bv;
    __syncthreads();

    const int KT = Kdim >> 3;
    int buf = 0;
    for (int kt = 0; kt < KT; ++kt) {
        if (kt + 1 < KT) {
            av = *(const float4*)(Aptr + (kt + 1) * 8);
            bv = *(const float4*)(Bptr + (size_t)(kt + 1) * 8 * ldb);
        }
        #pragma unroll
        for (int kk = 0; kk < 8; ++kk) {
            float a0[8], b0[8];
            *(float4*)&a0[0] = *(const float4*)&As[buf][kk][tr];
            *(float4*)&a0[4] = *(const float4*)&As[buf][kk][tr + 4];
            *(float4*)&b0[0] = *(const float4*)&Bs[buf][kk][tc];
            *(float4*)&b0[4] = *(const float4*)&Bs[buf][kk][tc + 4];
            #pragma unroll
            for (int i = 0; i < 8; ++i)
                #pragma unroll
                for (int j = 0; j < 8; ++j)
                    acc[i][j] += a0[i] * b0[j];
        }
        if (kt + 1 < KT) {
            buf ^= 1;
            As[buf][aCol + 0][aRow] = av.x; As[buf][aCol + 1][aRow] = av.y;
            As[buf][aCol + 2][aRow] = av.z; As[buf][aCol + 3][aRow] = av.w;
            *(float4*)&Bs[buf][bRow][bCol] = bv;
            __syncthreads();
        }
    }

    const int row0 = by * 128 + tr;
    const int col0 = bx * 128 + tc;
    #pragma unroll
    for (int i = 0; i < 8; ++i) {
        size_t off = (size_t)(row0 + i) * ldc + col0;
        float out[8];
        #pragma unroll
        for (int j = 0; j < 8; ++j) {
            float v = acc[i][j];
            if (OP == 1) v += X[off + j];
            out[j] = v;
        }
        *(float4*)&C[off]     = *(float4*)&out[0];
        *(float4*)&C[off + 4] = *(float4*)&out[4];
    }
}

// ---------------- state projections: Kp = state@Wk, V = state@Wv -------------
__global__ __launch_bounds__(256)
void state_proj_kernel(const float* __restrict__ state,
                       const float* __restrict__ Wk,
                       const float* __restrict__ Wv,
                       float* __restrict__ Kp, float* __restrict__ V)
{
    const float* B = (blockIdx.y == 0) ? Wk : Wv;
    float* C = (blockIdx.y == 0) ? Kp : V;
    const int bx = blockIdx.x;
    __shared__ float As[16][64];
    __shared__ float Bs[16][64];
    const int tid = threadIdx.x;
    const int rb = (tid >> 4) << 2;
    const int cb = (tid & 15) << 2;
    float acc[4][4];
    #pragma unroll
    for (int i = 0; i < 4; ++i)
        #pragma unroll
        for (int j = 0; j < 4; ++j) acc[i][j] = 0.f;

    for (int kt = 0; kt < 32; ++kt) {
        const int k0 = kt * 16;
        {
            int r = tid >> 2, c4 = (tid & 3) << 2;
            float4 v = *(const float4*)&state[r * 512 + k0 + c4];
            As[c4 + 0][r] = v.x; As[c4 + 1][r] = v.y;
            As[c4 + 2][r] = v.z; As[c4 + 3][r] = v.w;
        }
        {
            int r = tid >> 4, c4 = (tid & 15) << 2;
            *(float4*)&Bs[r][c4] = *(const float4*)&B[(k0 + r) * 512 + bx * 64 + c4];
        }
        __syncthreads();
        #pragma unroll
        for (int kk = 0; kk < 16; ++kk) {
            float a[4], b[4];
            *(float4*)a = *(const float4*)&As[kk][rb];
            *(float4*)b = *(const float4*)&Bs[kk][cb];
            #pragma unroll
            for (int i = 0; i < 4; ++i)
                #pragma unroll
                for (int j = 0; j < 4; ++j) acc[i][j] += a[i] * b[j];
        }
        __syncthreads();
    }
    #pragma unroll
    for (int i = 0; i < 4; ++i)
        *(float4*)&C[(rb + i) * 512 + bx * 64 + cb] = *(float4*)&acc[i][0];
}

// ---------------- C[M,64] = A[M,512] @ B64[64,512]^T (M1 / M2 builders) ------
__global__ __launch_bounds__(256)
void abt_kernel(const float* __restrict__ A,
                const float* __restrict__ B,
                float* __restrict__ C)
{
    const int r0 = blockIdx.x * 64;
    __shared__ float As[16][68];
    __shared__ float Bs[16][68];
    const int tid = threadIdx.x;
    const int rb = (tid >> 4) << 2;
    const int cb = (tid & 15) << 2;
    const int lr = tid >> 2, lc4 = (tid & 3) << 2;
    float acc[4][4];
    #pragma unroll
    for (int i = 0; i < 4; ++i)
        #pragma unroll
        for (int j = 0; j < 4; ++j) acc[i][j] = 0.f;

    for (int kt = 0; kt < 32; ++kt) {
        const int k0 = kt * 16;
        float4 va = *(const float4*)&A[(size_t)(r0 + lr) * 512 + k0 + lc4];
        float4 vb = *(const float4*)&B[(size_t)lr * 512 + k0 + lc4];
        As[lc4 + 0][lr] = va.x; As[lc4 + 1][lr] = va.y;
        As[lc4 + 2][lr] = va.z; As[lc4 + 3][lr] = va.w;
        Bs[lc4 + 0][lr] = vb.x; Bs[lc4 + 1][lr] = vb.y;
        Bs[lc4 + 2][lr] = vb.z; Bs[lc4 + 3][lr] = vb.w;
        __syncthreads();
        #pragma unroll
        for (int kk = 0; kk < 16; ++kk) {
            float a[4], b[4];
            *(float4*)a = *(const float4*)&As[kk][rb];
            *(float4*)b = *(const float4*)&Bs[kk][cb];
            #pragma unroll
            for (int i = 0; i < 4; ++i)
                #pragma unroll
                for (int j = 0; j < 4; ++j) acc[i][j] += a[i] * b[j];
        }
        __syncthreads();
    }
    #pragma unroll
    for (int i = 0; i < 4; ++i)
        *(float4*)&C[(size_t)(r0 + rb + i) * 64 + cb] = *(float4*)&acc[i][0];
}

// ---------------- C[64,NC] = A[64,512] @ B[512,NC]  (VWo builder) ------------
__global__ __launch_bounds__(256)
void smallab_kernel(const float* __restrict__ A,
                    const float* __restrict__ B,
                    float* __restrict__ C, int NC)
{
    const int n0 = blockIdx.x * 64;
    __shared__ float As[16][68];
    __shared__ float Bs[16][68];
    const int tid = threadIdx.x;
    const int rb = (tid >> 4) << 2;
    const int cb = (tid & 15) << 2;
    const int lr = tid >> 2, lc4 = (tid & 3) << 2;
    const int br = tid >> 4, bc4 = (tid & 15) << 2;
    float acc[4][4];
    #pragma unroll
    for (int i = 0; i < 4; ++i)
        #pragma unroll
        for (int j = 0; j < 4; ++j) acc[i][j] = 0.f;

    for (int kt = 0; kt < 32; ++kt) {
        const int k0 = kt * 16;
        float4 va = *(const float4*)&A[(size_t)lr * 512 + k0 + lc4];
        As[lc4 + 0][lr] = va.x; As[lc4 + 1][lr] = va.y;
        As[lc4 + 2][lr] = va.z; As[lc4 + 3][lr] = va.w;
        *(float4*)&Bs[br][bc4] =
            *(const float4*)&B[(size_t)(k0 + br) * NC + n0 + bc4];
        __syncthreads();
        #pragma unroll
        for (int kk = 0; kk < 16; ++kk) {
            float a[4], b[4];
            *(float4*)a = *(const float4*)&As[kk][rb];
            *(float4*)b = *(const float4*)&Bs[kk][cb];
            #pragma unroll
            for (int i = 0; i < 4; ++i)
                #pragma unroll
                for (int j = 0; j < 4; ++j) acc[i][j] += a[i] * b[j];
        }
        __syncthreads();
    }
    #pragma unroll
    for (int i = 0; i < 4; ++i)
        *(float4*)&C[(size_t)(rb + i) * NC + n0 + cb] = *(float4*)&acc[i][0];
}

// ------- fused logits GEMM (M x 64, B is [Kdim,64]) + row softmax (+gate) ----
__global__ __launch_bounds__(256)
void attn2_kernel(const float* __restrict__ A, int lda, int Kdim,
                  const float* __restrict__ Bm,   // [Kdim, 64]
                  float* __restrict__ out,        // [N,64]
                  float scale,
                  const float* __restrict__ gate) // nullable
{
    __shared__ float As[16][132];
    __shared__ float Bs[16][68];
    __shared__ float L[128][65];
    __shared__ float rmax[128], rfac[128];
    const int tid = threadIdx.x;
    const int row0 = blockIdx.x * 128;
    const int rb = (tid >> 4) << 3;
    const int cb = (tid & 15) << 2;
    float acc[8][4];
    #pragma unroll
    for (int i = 0; i < 8; ++i)
        #pragma unroll
        for (int j = 0; j < 4; ++j) acc[i][j] = 0.f;

    const int KT = Kdim >> 4;
    for (int kt = 0; kt < KT; ++kt) {
        const int k0 = kt * 16;
        #pragma unroll
        for (int j = 0; j < 2; ++j) {
            int f = tid + j * 256;
            int r = f >> 2, c4 = (f & 3) << 2;
            float4 v = *(const float4*)&A[(size_t)(row0 + r) * lda + k0 + c4];
            As[c4 + 0][r] = v.x; As[c4 + 1][r] = v.y;
            As[c4 + 2][r] = v.z; As[c4 + 3][r] = v.w;
        }
        {
            int r = tid >> 4, c4 = (tid & 15) << 2;
            *(float4*)&Bs[r][c4] = *(const float4*)&Bm[(size_t)(k0 + r) * 64 + c4];
        }
        __syncthreads();
        #pragma unroll
        for (int kk = 0; kk < 16; ++kk) {
            float a[8], b[4];
            *(float4*)&a[0] = *(const float4*)&As[kk][rb];
            *(float4*)&a[4] = *(const float4*)&As[kk][rb + 4];
            *(float4*)&b[0] = *(const float4*)&Bs[kk][cb];
            #pragma unroll
            for (int i = 0; i < 8; ++i)
                #pragma unroll
                for (int j = 0; j < 4; ++j) acc[i][j] += a[i] * b[j];
        }
        __syncthreads();
    }
    #pragma unroll
    for (int i = 0; i < 8; ++i)
        #pragma unroll
        for (int j = 0; j < 4; ++j) L[rb + i][cb + j] = acc[i][j] * scale;
    __syncthreads();
    if (tid < 128) {
        float m = -1e30f;
        for (int c = 0; c < 64; ++c) m = fmaxf(m, L[tid][c]);
        float s = 0.f;
        for (int c = 0; c < 64; ++c) s += expf(L[tid][c] - m);
        rmax[tid] = m;
        float g = gate ? gate[row0 + tid] : 1.f;
        rfac[tid] = g / s;
    }
    __syncthreads();
    #pragma unroll
    for (int t2 = 0; t2 < 32; ++t2) {
        int e = tid + t2 * 256;
        int r = e >> 6, c = e & 63;
        out[(size_t)(row0 + r) * 64 + c] = expf(L[r][c] - rmax[r]) * rfac[r];
    }
}

// ---------------- layernorm (row 1024) fused with write-gate dot -------------
__global__ __launch_bounds__(256)
void ln_gate_kernel(const float* __restrict__ T,
                    const float* __restrict__ gamma,
                    const float* __restrict__ beta,
                    const float* __restrict__ Wg,
                    const float* __restrict__ bgp,
                    float* __restrict__ H,
                    float* __restrict__ gate)
{
    __shared__ float sm[8], sm2[8];
    __shared__ float s_mu, s_inv;
    const int row = blockIdx.x;
    const int t = threadIdx.x;
    const size_t base = (size_t)row * 1024 + t * 4;
    float4 v = *(const float4*)&T[base];
    float s  = v.x + v.y + v.z + v.w;
    float sq = v.x * v.x + v.y * v.y + v.z * v.z + v.w * v.w;
    #pragma unroll
    for (int o = 16; o > 0; o >>= 1) {
        s  += __shfl_down_sync(0xffffffffu, s, o);
        sq += __shfl_down_sync(0xffffffffu, sq, o);
    }
    const int lane = t & 31, w = t >> 5;
    if (lane == 0) { sm[w] = s; sm2[w] = sq; }
    __syncthreads();
    if (t == 0) {
        float S = 0.f, Q = 0.f;
        #pragma unroll
        for (int i = 0; i < 8; ++i) { S += sm[i]; Q += sm2[i]; }
        float mu = S * (1.f / 1024.f);
        float var = Q * (1.f / 1024.f) - mu * mu;
        s_mu = mu; s_inv = rsqrtf(var + 1e-6f);
    }
    __syncthreads();
    const float mu = s_mu, inv = s_inv;
    float4 g4 = *(const float4*)&gamma[t * 4];
    float4 b4 = *(const float4*)&beta[t * 4];
    float4 h;
    h.x = (v.x - mu) * inv * g4.x + b4.x;
    h.y = (v.y - mu) * inv * g4.y + b4.y;
    h.z = (v.z - mu) * inv * g4.z + b4.z;
    h.w = (v.w - mu) * inv * g4.w + b4.w;
    *(float4*)&H[base] = h;
    float4 wg = *(const float4*)&Wg[t * 4];
    float gd = h.x * wg.x + h.y * wg.y + h.z * wg.z + h.w * wg.w;
    #pragma unroll
    for (int o = 16; o > 0; o >>= 1) gd += __shfl_down_sync(0xffffffffu, gd, o);
    __syncthreads();
    if (lane == 0) sm[w] = gd;
    __syncthreads();
    if (t == 0) {
        float G = 0.f;
        #pragma unroll
        for (int i = 0; i < 8; ++i) G += sm[i];
        gate[row] = 1.f / (1.f + expf(-(G + bgp[0])));
    }
}

// ---------------- split-K aggregation: agg[64,512] += W^T chunk @ E chunk ----
__global__ __launch_bounds__(256)
void agg_kernel(const float* __restrict__ Wt,
                const float* __restrict__ E,
                float* __restrict__ agg)
{
    const int sTile = blockIdx.x;
    const int r0 = blockIdx.y * 2048;
    __shared__ float Ws[16][64];
    __shared__ float Es[16][128];
    const int tid = threadIdx.x;
    const int slot0 = (tid >> 5) << 3;
    const int col0  = (tid & 31) << 2;
    float acc[8][4];
    #pragma unroll
    for (int i = 0; i < 8; ++i)
        #pragma unroll
        for (int j = 0; j < 4; ++j) acc[i][j] = 0.f;

    for (int kt = 0; kt < 128; ++kt) {
        const int rr = r0 + kt * 16;
        {
            int r = tid >> 4, c4 = (tid & 15) << 2;
            *(float4*)&Ws[r][c4] = *(const float4*)&Wt[(size_t)(rr + r) * 64 + c4];
        }
        #pragma unroll
        for (int j = 0; j < 2; ++j) {
            int f = tid + j * 256;
            int r = f >> 5, c4 = (f & 31) << 2;
            *(float4*)&Es[r][c4] =
                *(const float4*)&E[(size_t)(rr + r) * 512 + sTile * 128 + c4];
        }
        __syncthreads();
        #pragma unroll
        for (int kk = 0; kk < 16; ++kk) {
            float w[8], e[4];
            *(float4*)&w[0] = *(const float4*)&Ws[kk][slot0];
            *(float4*)&w[4] = *(const float4*)&Ws[kk][slot0 + 4];
            *(float4*)&e[0] = *(const float4*)&Es[kk][col0];
            #pragma unroll
            for (int i = 0; i < 8; ++i)
                #pragma unroll
                for (int j = 0; j < 4; ++j) acc[i][j] += w[i] * e[j];
        }
        __syncthreads();
    }
    #pragma unroll
    for (int i = 0; i < 8; ++i)
        #pragma unroll
        for (int j = 0; j < 4; ++j)
            atomicAdd(&agg[(slot0 + i) * 512 + sTile * 128 + col0 + j], acc[i][j]);
}

__global__ void zero_kernel(float* p, int n) {
    int i = blockIdx.x * blockDim.x + threadIdx.x;
    if (i < n) p[i] = 0.f;
}

__global__ void final_state_kernel(const float* __restrict__ state,
                                   const float* __restrict__ er,
                                   const float* __restrict__ wr,
                                   float* __restrict__ out)
{
    int i = blockIdx.x * blockDim.x + threadIdx.x;
    float e = fminf(fmaxf(er[i], 0.f), 1.f);
    out[i] = state[i] * (1.f - e) + wr[i];
}

// ------------------------------- launch --------------------------------------
extern "C" void kernel_launch(void* const* d_in, const int* in_sizes, int n_in,
                              void* d_out, int out_size)
{
    const float* X     = (const float*)d_in[0];
    const float* state = (const float*)d_in[1];
    const float* Wq    = (const float*)d_in[2];
    const float* Wk    = (const float*)d_in[3];
    const float* Wv    = (const float*)d_in[4];
    const float* Wo    = (const float*)d_in[5];
    const float* gamma = (const float*)d_in[6];
    const float* beta  = (const float*)d_in[7];
    const float* Wa    = (const float*)d_in[8];
    const float* Wg    = (const float*)d_in[9];
    const float* bg    = (const float*)d_in[10];
    const float* We    = (const float*)d_in[11];
    const float* be    = (const float*)d_in[12];
    const float* Wc    = (const float*)d_in[13];
    const float* bc    = (const float*)d_in[14];
    float* out = (float*)d_out;

    float *pE, *pC, *pT, *pAttn, *pGate, *pKp, *pV, *pM1, *pM2, *pVWo, *pAgg;
    cudaGetSymbolAddress((void**)&pE, g_E);
    cudaGetSymbolAddress((void**)&pC, g_C);
    cudaGetSymbolAddress((void**)&pT, g_T);
    cudaGetSymbolAddress((void**)&pAttn, g_attn);
    cudaGetSymbolAddress((void**)&pGate, g_gate);
    cudaGetSymbolAddress((void**)&pKp, g_Kp);
    cudaGetSymbolAddress((void**)&pV, g_V);
    cudaGetSymbolAddress((void**)&pM1, g_M1);
    cudaGetSymbolAddress((void**)&pM2, g_M2);
    cudaGetSymbolAddress((void**)&pVWo, g_VWo);
    cudaGetSymbolAddress((void**)&pAgg, g_agg);
    float* pAgg0 = pAgg;
    float* pAgg1 = pAgg + KSLOTS * SDIM;

    const float scale = 1.0f / sqrtf((float)SDIM);

    zero_kernel<<<128, 512>>>(pAgg, 2 * KSLOTS * SDIM);

    // Kp = state@Wk, V = state@Wv
    state_proj_kernel<<<dim3(8, 2), 256>>>(state, Wk, Wv, pKp, pV);

    // M1 = Wq @ Kp^T [1024,64];  M2 = Wa @ state^T [1024,64]
    abt_kernel<<<16, 256>>>(Wq, pKp, pM1);
    abt_kernel<<<16, 256>>>(Wa, state, pM2);

    // VWo = V @ Wo [64,1024]
    smallab_kernel<<<16, 256>>>(pV, Wo, pVWo, DDIM);

    // attn = softmax(X @ M1 * scale)
    attn2_kernel<<<512, 256>>>(X, DDIM, DDIM, pM1, pAttn, scale, nullptr);

    // T = X + attn @ VWo
    sgemm128<1><<<dim3(8, 512), 256>>>(pAttn, KSLOTS, pVWo, DDIM, pT, DDIM,
                                       KSLOTS, X);

    // h = LN(T) -> out[0:N*D]; gate = sigmoid(h.Wg + bg)
    ln_gate_kernel<<<NROWS, 256>>>(pT, gamma, beta, Wg, bg, out, pGate);

    // weighted = gate * softmax(h @ M2)
    attn2_kernel<<<512, 256>>>(out, DDIM, DDIM, pM2, pAttn, 1.0f, pGate);

    // E = sigmoid(h@We+be), C = tanh(h@Wc+bc)  (tf32 tensor cores)
    tf32gemm<2><<<dim3(4, 512), 256>>>(out, We, pE, be);
    tf32gemm<3><<<dim3(4, 512), 256>>>(out, Wc, pC, bc);

    // erase_agg / write_agg
    agg_kernel<<<dim3(4, 32), 256>>>(pAttn, pE, pAgg0);
    agg_kernel<<<dim3(4, 32), 256>>>(pAttn, pC, pAgg1);

    // new_state -> out[N*D:]
    final_state_kernel<<<64, 512>>>(state, pAgg0, pAgg1,
                                    out + (size_t)NROWS * DDIM);
}

// round 10
// speedup vs baseline: 4.1363x; 1.1853x over previous
#include <cuda_runtime.h>
#include <math.h>
#include <stdint.h>

#define NROWS 65536
#define DDIM  1024
#define SDIM  512
#define KSLOTS 64

// ---------------- scratch (device globals; no allocation allowed) ------------
__device__ float g_E[NROWS * SDIM];       // erase_vec
__device__ float g_C[NROWS * SDIM];       // content
__device__ float g_T[NROWS * DDIM];       // x + read_out (pre-LN)
__device__ float g_attn[NROWS * KSLOTS];  // attn -> weighted (reused)
__device__ float g_gate[NROWS];           // write gate
// small atomic-target workspace: Kp | V | M1 | M2 | VWo | aggE | aggC
#define OFF_KP   0
#define OFF_V    32768
#define OFF_M1   65536
#define OFF_M2   131072
#define OFF_VWO  196608
#define OFF_AGG  262144
#define WS_TOTAL 327680
__device__ float g_ws[WS_TOTAL];

// ---------------- tf32 helpers ----------------------------------------------
__device__ __forceinline__ uint32_t f2tf(float x) {
    uint32_t t; asm("cvt.rna.tf32.f32 %0, %1;" : "=r"(t) : "f"(x)); return t;
}
__device__ __forceinline__ void st4tf(uint32_t* p, float4 v) {
    p[0] = f2tf(v.x); p[1] = f2tf(v.y); p[2] = f2tf(v.z); p[3] = f2tf(v.w);
}
__device__ __forceinline__ void mma_tf32(float* d, const uint32_t* a,
                                         const uint32_t* b) {
    asm volatile(
        "mma.sync.aligned.m16n8k8.row.col.f32.tf32.tf32.f32 "
        "{%0,%1,%2,%3}, {%4,%5,%6,%7}, {%8,%9}, {%0,%1,%2,%3};\n"
        : "+f"(d[0]), "+f"(d[1]), "+f"(d[2]), "+f"(d[3])
        : "r"(a[0]), "r"(a[1]), "r"(a[2]), "r"(a[3]), "r"(b[0]), "r"(b[1]));
}

// ================= tf32 tensor-core GEMM: C = act(A[M,1024]@B[1024,512]+bias)
template<int OP>  // 2 = sigmoid(acc+bias), 3 = tanh(acc+bias)
__global__ __launch_bounds__(256)
void tf32gemm(const float* __restrict__ A,
              const float* __restrict__ B,
              float* __restrict__ C,
              const float* __restrict__ bias)
{
    __shared__ uint32_t As[2][128][20];
    __shared__ uint32_t Bs[2][16][136];
    const int tid = threadIdx.x;
    const int bx = blockIdx.x, by = blockIdx.y;
    const int lane = tid & 31;
    const int w = tid >> 5;
    const int wm = w & 1, wn = w >> 1;
    const int g = lane >> 2, cc = lane & 3;

    const int ar = tid >> 2, ac = (tid & 3) << 2;
    const int br = tid >> 5, bc = (tid & 31) << 2;

    const float* Ag = A + (size_t)(by * 128 + ar) * 1024 + ac;
    const float* Bg = B + (size_t)br * 512 + bx * 128 + bc;

    float acc[4][4][4];
    #pragma unroll
    for (int i = 0; i < 4; ++i)
        #pragma unroll
        for (int j = 0; j < 4; ++j)
            #pragma unroll
            for (int r = 0; r < 4; ++r) acc[i][j][r] = 0.f;

    float4 a0v = *(const float4*)Ag;
    float4 a1v = *(const float4*)(Ag + (size_t)64 * 1024);
    float4 b0v = *(const float4*)Bg;
    float4 b1v = *(const float4*)(Bg + (size_t)8 * 512);
    st4tf(&As[0][ar][ac], a0v);
    st4tf(&As[0][ar + 64][ac], a1v);
    st4tf(&Bs[0][br][bc], b0v);
    st4tf(&Bs[0][br + 8][bc], b1v);
    __syncthreads();

    int buf = 0;
    for (int kt = 0; kt < 64; ++kt) {
        if (kt < 63) {
            a0v = *(const float4*)(Ag + (kt + 1) * 16);
            a1v = *(const float4*)(Ag + (kt + 1) * 16 + (size_t)64 * 1024);
            b0v = *(const float4*)(Bg + (size_t)(kt + 1) * 16 * 512);
            b1v = *(const float4*)(Bg + (size_t)((kt + 1) * 16 + 8) * 512);
        }
        #pragma unroll
        for (int s = 0; s < 2; ++s) {
            const int kk = s * 8;
            uint32_t af[4][4], bf[4][2];
            #pragma unroll
            for (int i = 0; i < 4; ++i) {
                const int m = wm * 64 + i * 16 + g;
                af[i][0] = As[buf][m][kk + cc];
                af[i][1] = As[buf][m + 8][kk + cc];
                af[i][2] = As[buf][m][kk + cc + 4];
                af[i][3] = As[buf][m + 8][kk + cc + 4];
            }
            #pragma unroll
            for (int j = 0; j < 4; ++j) {
                const int n = wn * 32 + j * 8 + g;
                bf[j][0] = Bs[buf][kk + cc][n];
                bf[j][1] = Bs[buf][kk + cc + 4][n];
            }
            #pragma unroll
            for (int i = 0; i < 4; ++i)
                #pragma unroll
                for (int j = 0; j < 4; ++j)
                    mma_tf32(acc[i][j], af[i], bf[j]);
        }
        if (kt < 63) {
            buf ^= 1;
            st4tf(&As[buf][ar][ac], a0v);
            st4tf(&As[buf][ar + 64][ac], a1v);
            st4tf(&Bs[buf][br][bc], b0v);
            st4tf(&Bs[buf][br + 8][bc], b1v);
            __syncthreads();
        }
    }

    #pragma unroll
    for (int i = 0; i < 4; ++i) {
        const int row = by * 128 + wm * 64 + i * 16 + g;
        #pragma unroll
        for (int j = 0; j < 4; ++j) {
            const int col = bx * 128 + wn * 32 + j * 8 + 2 * cc;
            const float bb0 = bias[col], bb1 = bias[col + 1];
            float v0 = acc[i][j][0] + bb0, v1 = acc[i][j][1] + bb1;
            float v2 = acc[i][j][2] + bb0, v3 = acc[i][j][3] + bb1;
            if (OP == 2) {
                v0 = 1.f / (1.f + expf(-v0)); v1 = 1.f / (1.f + expf(-v1));
                v2 = 1.f / (1.f + expf(-v2)); v3 = 1.f / (1.f + expf(-v3));
            } else {
                v0 = tanhf(v0); v1 = tanhf(v1);
                v2 = tanhf(v2); v3 = tanhf(v3);
            }
            float2 p0; p0.x = v0; p0.y = v1;
            float2 p1; p1.x = v2; p1.y = v3;
            *(float2*)&C[(size_t)row * 512 + col] = p0;
            *(float2*)&C[(size_t)(row + 8) * 512 + col] = p1;
        }
    }
}

// ====== attn #1 (read): tf32 GEMM [128x64, K=1024] + register softmax ========
__global__ __launch_bounds__(256)
void attn1_tf32_kernel(const float* __restrict__ A,   // [N,1024]
                       const float* __restrict__ Bm,  // [1024,64]
                       float* __restrict__ out,       // [N,64]
                       float scale)
{
    __shared__ uint32_t As[2][128][20];
    __shared__ uint32_t Bs[2][16][72];
    const int tid = threadIdx.x;
    const int lane = tid & 31, w = tid >> 5;
    const int g = lane >> 2, cc = lane & 3;
    const int m0 = w << 4;                 // warp = one m16 tile
    const int row0 = blockIdx.x * 128;

    const int ar = tid >> 1, ak = (tid & 1) << 3;
    const int br = tid >> 4, bn = (tid & 15) << 2;
    const float* Ag = A + (size_t)(row0 + ar) * 1024 + ak;
    const float* Bg = Bm + (size_t)br * 64 + bn;

    float acc[8][4];
    #pragma unroll
    for (int i = 0; i < 8; ++i)
        #pragma unroll
        for (int j = 0; j < 4; ++j) acc[i][j] = 0.f;

    float4 a0 = *(const float4*)Ag;
    float4 a1 = *(const float4*)(Ag + 4);
    float4 bv = *(const float4*)Bg;
    st4tf(&As[0][ar][ak], a0);
    st4tf(&As[0][ar][ak + 4], a1);
    st4tf(&Bs[0][br][bn], bv);
    __syncthreads();

    int buf = 0;
    for (int kt = 0; kt < 64; ++kt) {
        if (kt < 63) {
            a0 = *(const float4*)(Ag + (kt + 1) * 16);
            a1 = *(const float4*)(Ag + (kt + 1) * 16 + 4);
            bv = *(const float4*)(Bg + (size_t)(kt + 1) * 16 * 64);
        }
        #pragma unroll
        for (int s = 0; s < 2; ++s) {
            const int kk = s * 8;
            uint32_t af[4];
            af[0] = As[buf][m0 + g][kk + cc];
            af[1] = As[buf][m0 + g + 8][kk + cc];
            af[2] = As[buf][m0 + g][kk + cc + 4];
            af[3] = As[buf][m0 + g + 8][kk + cc + 4];
            #pragma unroll
            for (int nt = 0; nt < 8; ++nt) {
                uint32_t bf[2];
                bf[0] = Bs[buf][kk + cc][nt * 8 + g];
                bf[1] = Bs[buf][kk + cc + 4][nt * 8 + g];
                mma_tf32(acc[nt], af, bf);
            }
        }
        if (kt < 63) {
            buf ^= 1;
            st4tf(&As[buf][ar][ak], a0);
            st4tf(&As[buf][ar][ak + 4], a1);
            st4tf(&Bs[buf][br][bn], bv);
            __syncthreads();
        }
    }

    // rows (m0+g) and (m0+g+8); their 64 cols live in this quad (lanes g*4..+3)
    float mx0 = -1e30f, mx1 = -1e30f;
    #pragma unroll
    for (int nt = 0; nt < 8; ++nt) {
        mx0 = fmaxf(mx0, fmaxf(acc[nt][0], acc[nt][1]));
        mx1 = fmaxf(mx1, fmaxf(acc[nt][2], acc[nt][3]));
    }
    #pragma unroll
    for (int s2 = 1; s2 <= 2; s2 <<= 1) {
        mx0 = fmaxf(mx0, __shfl_xor_sync(0xffffffffu, mx0, s2));
        mx1 = fmaxf(mx1, __shfl_xor_sync(0xffffffffu, mx1, s2));
    }
    mx0 *= scale; mx1 *= scale;
    float s0 = 0.f, s1 = 0.f;
    #pragma unroll
    for (int nt = 0; nt < 8; ++nt) {
        acc[nt][0] = expf(acc[nt][0] * scale - mx0);
        acc[nt][1] = expf(acc[nt][1] * scale - mx0);
        acc[nt][2] = expf(acc[nt][2] * scale - mx1);
        acc[nt][3] = expf(acc[nt][3] * scale - mx1);
        s0 += acc[nt][0] + acc[nt][1];
        s1 += acc[nt][2] + acc[nt][3];
    }
    #pragma unroll
    for (int s2 = 1; s2 <= 2; s2 <<= 1) {
        s0 += __shfl_xor_sync(0xffffffffu, s0, s2);
        s1 += __shfl_xor_sync(0xffffffffu, s1, s2);
    }
    const float f0 = 1.f / s0, f1 = 1.f / s1;
    const int ra = row0 + m0 + g;
    #pragma unroll
    for (int nt = 0; nt < 8; ++nt) {
        const int col = nt * 8 + 2 * cc;
        float2 p0; p0.x = acc[nt][0] * f0; p0.y = acc[nt][1] * f0;
        float2 p1; p1.x = acc[nt][2] * f1; p1.y = acc[nt][3] * f1;
        *(float2*)&out[(size_t)ra * 64 + col] = p0;
        *(float2*)&out[(size_t)(ra + 8) * 64 + col] = p1;
    }
}

// ====== attn #2 (addr): fp32 GEMM [128x64] + half-warp shuffle softmax =======
__global__ __launch_bounds__(256)
void attn2_kernel(const float* __restrict__ A, int lda, int Kdim,
                  const float* __restrict__ Bm,   // [Kdim, 64]
                  float* __restrict__ out,        // [N,64]
                  float scale,
                  const float* __restrict__ gate)
{
    __shared__ float As[16][132];
    __shared__ float Bs[16][68];
    const int tid = threadIdx.x;
    const int row0 = blockIdx.x * 128;
    const int rb = (tid >> 4) << 3;
    const int cb = (tid & 15) << 2;
    float acc[8][4];
    #pragma unroll
    for (int i = 0; i < 8; ++i)
        #pragma unroll
        for (int j = 0; j < 4; ++j) acc[i][j] = 0.f;

    const int KT = Kdim >> 4;
    for (int kt = 0; kt < KT; ++kt) {
        const int k0 = kt * 16;
        #pragma unroll
        for (int j = 0; j < 2; ++j) {
            int f = tid + j * 256;
            int r = f >> 2, c4 = (f & 3) << 2;
            float4 v = *(const float4*)&A[(size_t)(row0 + r) * lda + k0 + c4];
            As[c4 + 0][r] = v.x; As[c4 + 1][r] = v.y;
            As[c4 + 2][r] = v.z; As[c4 + 3][r] = v.w;
        }
        {
            int r = tid >> 4, c4 = (tid & 15) << 2;
            *(float4*)&Bs[r][c4] = *(const float4*)&Bm[(size_t)(k0 + r) * 64 + c4];
        }
        __syncthreads();
        #pragma unroll
        for (int kk = 0; kk < 16; ++kk) {
            float a[8], b[4];
            *(float4*)&a[0] = *(const float4*)&As[kk][rb];
            *(float4*)&a[4] = *(const float4*)&As[kk][rb + 4];
            *(float4*)&b[0] = *(const float4*)&Bs[kk][cb];
            #pragma unroll
            for (int i = 0; i < 8; ++i)
                #pragma unroll
                for (int j = 0; j < 4; ++j) acc[i][j] += a[i] * b[j];
        }
        __syncthreads();
    }
    // row rb+i lives in the 16 threads with same tid>>4 (one half-warp)
    #pragma unroll
    for (int i = 0; i < 8; ++i) {
        float l0 = acc[i][0] * scale, l1 = acc[i][1] * scale;
        float l2 = acc[i][2] * scale, l3 = acc[i][3] * scale;
        float m = fmaxf(fmaxf(l0, l1), fmaxf(l2, l3));
        #pragma unroll
        for (int s2 = 1; s2 <= 8; s2 <<= 1)
            m = fmaxf(m, __shfl_xor_sync(0xffffffffu, m, s2));
        float e0 = expf(l0 - m), e1 = expf(l1 - m);
        float e2 = expf(l2 - m), e3 = expf(l3 - m);
        float sum = e0 + e1 + e2 + e3;
        #pragma unroll
        for (int s2 = 1; s2 <= 8; s2 <<= 1)
            sum += __shfl_xor_sync(0xffffffffu, sum, s2);
        const int row = row0 + rb + i;
        const float fac = (gate ? gate[row] : 1.f) / sum;
        float4 o; o.x = e0 * fac; o.y = e1 * fac; o.z = e2 * fac; o.w = e3 * fac;
        *(float4*)&out[(size_t)row * 64 + cb] = o;
    }
}

// ---------------- generic 128x128x8 SGEMM (K=64 read GEMM, +residual) --------
template<int OP>
__global__ __launch_bounds__(256, 2)
void sgemm128(const float* __restrict__ A, int lda,
              const float* __restrict__ B, int ldb,
              float* __restrict__ C, int ldc,
              int Kdim,
              const float* __restrict__ X)
{
    __shared__ float As[2][8][128];
    __shared__ float Bs[2][8][128];
    const int tid = threadIdx.x;
    const int bx = blockIdx.x, by = blockIdx.y;
    const int tr = (tid >> 4) << 3;
    const int tc = (tid & 15) << 3;

    const int aRow = tid >> 1;
    const int aCol = (tid & 1) << 2;
    const int bRow = tid >> 5;
    const int bCol = (tid & 31) << 2;

    const float* Aptr = A + (size_t)(by * 128 + aRow) * lda + aCol;
    const float* Bptr = B + (size_t)bRow * ldb + bx * 128 + bCol;

    float acc[8][8];
    #pragma unroll
    for (int i = 0; i < 8; ++i)
        #pragma unroll
        for (int j = 0; j < 8; ++j) acc[i][j] = 0.f;

    float4 av = *(const float4*)Aptr;
    float4 bv = *(const float4*)Bptr;
    As[0][aCol + 0][aRow] = av.x; As[0][aCol + 1][aRow] = av.y;
    As[0][aCol + 2][aRow] = av.z; As[0][aCol + 3][aRow] = av.w;
    *(float4*)&Bs[0][bRow][bCol] = bv;
    __syncthreads();

    const int KT = Kdim >> 3;
    int buf = 0;
    for (int kt = 0; kt < KT; ++kt) {
        if (kt + 1 < KT) {
            av = *(const float4*)(Aptr + (kt + 1) * 8);
            bv = *(const float4*)(Bptr + (size_t)(kt + 1) * 8 * ldb);
        }
        #pragma unroll
        for (int kk = 0; kk < 8; ++kk) {
            float a0[8], b0[8];
            *(float4*)&a0[0] = *(const float4*)&As[buf][kk][tr];
            *(float4*)&a0[4] = *(const float4*)&As[buf][kk][tr + 4];
            *(float4*)&b0[0] = *(const float4*)&Bs[buf][kk][tc];
            *(float4*)&b0[4] = *(const float4*)&Bs[buf][kk][tc + 4];
            #pragma unroll
            for (int i = 0; i < 8; ++i)
                #pragma unroll
                for (int j = 0; j < 8; ++j)
                    acc[i][j] += a0[i] * b0[j];
        }
        if (kt + 1 < KT) {
            buf ^= 1;
            As[buf][aCol + 0][aRow] = av.x; As[buf][aCol + 1][aRow] = av.y;
            As[buf][aCol + 2][aRow] = av.z; As[buf][aCol + 3][aRow] = av.w;
            *(float4*)&Bs[buf][bRow][bCol] = bv;
            __syncthreads();
        }
    }

    const int row0 = by * 128 + tr;
    const int col0 = bx * 128 + tc;
    #pragma unroll
    for (int i = 0; i < 8; ++i) {
        size_t off = (size_t)(row0 + i) * ldc + col0;
        float outv[8];
        #pragma unroll
        for (int j = 0; j < 8; ++j) {
            float v = acc[i][j];
            if (OP == 1) v += X[off + j];
            outv[j] = v;
        }
        *(float4*)&C[off]     = *(float4*)&outv[0];
        *(float4*)&C[off + 4] = *(float4*)&outv[4];
    }
}

// -------- state projections (split-K x4, atomic): Kp=state@Wk, V=state@Wv ----
__global__ __launch_bounds__(256)
void state_proj_kernel(const float* __restrict__ state,
                       const float* __restrict__ Wk,
                       const float* __restrict__ Wv,
                       float* __restrict__ Kp, float* __restrict__ V)
{
    const float* B = (blockIdx.y == 0) ? Wk : Wv;
    float* C = (blockIdx.y == 0) ? Kp : V;
    const int bx = blockIdx.x;
    const int kz = blockIdx.z;
    __shared__ float As[16][64];
    __shared__ float Bs[16][64];
    const int tid = threadIdx.x;
    const int rb = (tid >> 4) << 2;
    const int cb = (tid & 15) << 2;
    float acc[4][4];
    #pragma unroll
    for (int i = 0; i < 4; ++i)
        #pragma unroll
        for (int j = 0; j < 4; ++j) acc[i][j] = 0.f;

    for (int kt = kz * 8; kt < kz * 8 + 8; ++kt) {
        const int k0 = kt * 16;
        {
            int r = tid >> 2, c4 = (tid & 3) << 2;
            float4 v = *(const float4*)&state[r * 512 + k0 + c4];
            As[c4 + 0][r] = v.x; As[c4 + 1][r] = v.y;
            As[c4 + 2][r] = v.z; As[c4 + 3][r] = v.w;
        }
        {
            int r = tid >> 4, c4 = (tid & 15) << 2;
            *(float4*)&Bs[r][c4] = *(const float4*)&B[(k0 + r) * 512 + bx * 64 + c4];
        }
        __syncthreads();
        #pragma unroll
        for (int kk = 0; kk < 16; ++kk) {
            float a[4], b[4];
            *(float4*)a = *(const float4*)&As[kk][rb];
            *(float4*)b = *(const float4*)&Bs[kk][cb];
            #pragma unroll
            for (int i = 0; i < 4; ++i)
                #pragma unroll
                for (int j = 0; j < 4; ++j) acc[i][j] += a[i] * b[j];
        }
        __syncthreads();
    }
    #pragma unroll
    for (int i = 0; i < 4; ++i)
        #pragma unroll
        for (int j = 0; j < 4; ++j)
            atomicAdd(&C[(rb + i) * 512 + bx * 64 + cb + j], acc[i][j]);
}

// ----- C[M,64] = A[M,512] @ B64[64,512]^T (split-K x4, atomic) ---------------
__global__ __launch_bounds__(256)
void abt_kernel(const float* __restrict__ A,
                const float* __restrict__ B,
                float* __restrict__ C)
{
    const int r0 = blockIdx.x * 64;
    const int kz = blockIdx.y;
    __shared__ float As[16][68];
    __shared__ float Bs[16][68];
    const int tid = threadIdx.x;
    const int rb = (tid >> 4) << 2;
    const int cb = (tid & 15) << 2;
    const int lr = tid >> 2, lc4 = (tid & 3) << 2;
    float acc[4][4];
    #pragma unroll
    for (int i = 0; i < 4; ++i)
        #pragma unroll
        for (int j = 0; j < 4; ++j) acc[i][j] = 0.f;

    for (int kt = kz * 8; kt < kz * 8 + 8; ++kt) {
        const int k0 = kt * 16;
        float4 va = *(const float4*)&A[(size_t)(r0 + lr) * 512 + k0 + lc4];
        float4 vb = *(const float4*)&B[(size_t)lr * 512 + k0 + lc4];
        As[lc4 + 0][lr] = va.x; As[lc4 + 1][lr] = va.y;
        As[lc4 + 2][lr] = va.z; As[lc4 + 3][lr] = va.w;
        Bs[lc4 + 0][lr] = vb.x; Bs[lc4 + 1][lr] = vb.y;
        Bs[lc4 + 2][lr] = vb.z; Bs[lc4 + 3][lr] = vb.w;
        __syncthreads();
        #pragma unroll
        for (int kk = 0; kk < 16; ++kk) {
            float a[4], b[4];
            *(float4*)a = *(const float4*)&As[kk][rb];
            *(float4*)b = *(const float4*)&Bs[kk][cb];
            #pragma unroll
            for (int i = 0; i < 4; ++i)
                #pragma unroll
                for (int j = 0; j < 4; ++j) acc[i][j] += a[i] * b[j];
        }
        __syncthreads();
    }
    #pragma unroll
    for (int i = 0; i < 4; ++i)
        #pragma unroll
        for (int j = 0; j < 4; ++j)
            atomicAdd(&C[(size_t)(r0 + rb + i) * 64 + cb + j], acc[i][j]);
}

// ----- C[64,NC] = A[64,512] @ B[512,NC] (split-K x4, atomic; VWo builder) ----
__global__ __launch_bounds__(256)
void smallab_kernel(const float* __restrict__ A,
                    const float* __restrict__ B,
                    float* __restrict__ C, int NC)
{
    const int n0 = blockIdx.x * 64;
    const int kz = blockIdx.y;
    __shared__ float As[16][68];
    __shared__ float Bs[16][68];
    const int tid = threadIdx.x;
    const int rb = (tid >> 4) << 2;
    const int cb = (tid & 15) << 2;
    const int lr = tid >> 2, lc4 = (tid & 3) << 2;
    const int br = tid >> 4, bc4 = (tid & 15) << 2;
    float acc[4][4];
    #pragma unroll
    for (int i = 0; i < 4; ++i)
        #pragma unroll
        for (int j = 0; j < 4; ++j) acc[i][j] = 0.f;

    for (int kt = kz * 8; kt < kz * 8 + 8; ++kt) {
        const int k0 = kt * 16;
        float4 va = *(const float4*)&A[(size_t)lr * 512 + k0 + lc4];
        As[lc4 + 0][lr] = va.x; As[lc4 + 1][lr] = va.y;
        As[lc4 + 2][lr] = va.z; As[lc4 + 3][lr] = va.w;
        *(float4*)&Bs[br][bc4] =
            *(const float4*)&B[(size_t)(k0 + br) * NC + n0 + bc4];
        __syncthreads();
        #pragma unroll
        for (int kk = 0; kk < 16; ++kk) {
            float a[4], b[4];
            *(float4*)a = *(const float4*)&As[kk][rb];
            *(float4*)b = *(const float4*)&Bs[kk][cb];
            #pragma unroll
            for (int i = 0; i < 4; ++i)
                #pragma unroll
                for (int j = 0; j < 4; ++j) acc[i][j] += a[i] * b[j];
        }
        __syncthreads();
    }
    #pragma unroll
    for (int i = 0; i < 4; ++i)
        #pragma unroll
        for (int j = 0; j < 4; ++j)
            atomicAdd(&C[(size_t)(rb + i) * NC + n0 + cb + j], acc[i][j]);
}

// ---------------- layernorm (row 1024) fused with write-gate dot -------------
__global__ __launch_bounds__(256)
void ln_gate_kernel(const float* __restrict__ T,
                    const float* __restrict__ gamma,
                    const float* __restrict__ beta,
                    const float* __restrict__ Wg,
                    const float* __restrict__ bgp,
                    float* __restrict__ H,
                    float* __restrict__ gate)
{
    __shared__ float sm[8], sm2[8];
    __shared__ float s_mu, s_inv;
    const int row = blockIdx.x;
    const int t = threadIdx.x;
    const size_t base = (size_t)row * 1024 + t * 4;
    float4 v = *(const float4*)&T[base];
    float s  = v.x + v.y + v.z + v.w;
    float sq = v.x * v.x + v.y * v.y + v.z * v.z + v.w * v.w;
    #pragma unroll
    for (int o = 16; o > 0; o >>= 1) {
        s  += __shfl_down_sync(0xffffffffu, s, o);
        sq += __shfl_down_sync(0xffffffffu, sq, o);
    }
    const int lane = t & 31, w = t >> 5;
    if (lane == 0) { sm[w] = s; sm2[w] = sq; }
    __syncthreads();
    if (t == 0) {
        float S = 0.f, Q = 0.f;
        #pragma unroll
        for (int i = 0; i < 8; ++i) { S += sm[i]; Q += sm2[i]; }
        float mu = S * (1.f / 1024.f);
        float var = Q * (1.f / 1024.f) - mu * mu;
        s_mu = mu; s_inv = rsqrtf(var + 1e-6f);
    }
    __syncthreads();
    const float mu = s_mu, inv = s_inv;
    float4 g4 = *(const float4*)&gamma[t * 4];
    float4 b4 = *(const float4*)&beta[t * 4];
    float4 h;
    h.x = (v.x - mu) * inv * g4.x + b4.x;
    h.y = (v.y - mu) * inv * g4.y + b4.y;
    h.z = (v.z - mu) * inv * g4.z + b4.z;
    h.w = (v.w - mu) * inv * g4.w + b4.w;
    *(float4*)&H[base] = h;
    float4 wg = *(const float4*)&Wg[t * 4];
    float gd = h.x * wg.x + h.y * wg.y + h.z * wg.z + h.w * wg.w;
    #pragma unroll
    for (int o = 16; o > 0; o >>= 1) gd += __shfl_down_sync(0xffffffffu, gd, o);
    __syncthreads();
    if (lane == 0) sm[w] = gd;
    __syncthreads();
    if (t == 0) {
        float G = 0.f;
        #pragma unroll
        for (int i = 0; i < 8; ++i) G += sm[i];
        gate[row] = 1.f / (1.f + expf(-(G + bgp[0])));
    }
}

// ====== fused tf32 aggregation: aggE += W^T@E, aggC += W^T@C (split-K) =======
__global__ __launch_bounds__(256)
void agg2_tf32_kernel(const float* __restrict__ Wt,  // weighted [N,64]
                      const float* __restrict__ E,   // [N,512]
                      const float* __restrict__ C,   // [N,512]
                      float* __restrict__ aggE,
                      float* __restrict__ aggC)
{
    __shared__ uint32_t As[64][20];
    __shared__ uint32_t Es[16][136];
    __shared__ uint32_t Cs[16][136];
    const int tid = threadIdx.x;
    const int lane = tid & 31, w = tid >> 5;
    const int g = lane >> 2, cc = lane & 3;
    const int wm = w & 1, wn = w >> 1;
    const int col0 = blockIdx.x * 128;
    const int r0 = blockIdx.y * 2048;

    const int wrow = tid & 15;             // W load: row within 16-chunk
    const int wslot = (tid >> 4) << 2;     // W load: slot base
    const int er = tid >> 4;               // E/C load: row
    const int ec = (tid & 15) << 3;        // E/C load: col base

    float accE[2][4][4], accC[2][4][4];
    #pragma unroll
    for (int i = 0; i < 2; ++i)
        #pragma unroll
        for (int j = 0; j < 4; ++j)
            #pragma unroll
            for (int r = 0; r < 4; ++r) { accE[i][j][r] = 0.f; accC[i][j][r] = 0.f; }

    for (int it = 0; it < 128; ++it) {
        const int rr = r0 + it * 16;
        float4 wv = *(const float4*)&Wt[(size_t)(rr + wrow) * 64 + wslot];
        As[wslot + 0][wrow] = f2tf(wv.x);
        As[wslot + 1][wrow] = f2tf(wv.y);
        As[wslot + 2][wrow] = f2tf(wv.z);
        As[wslot + 3][wrow] = f2tf(wv.w);
        const size_t ebase = (size_t)(rr + er) * 512 + col0 + ec;
        float4 e0 = *(const float4*)&E[ebase];
        float4 e1 = *(const float4*)&E[ebase + 4];
        float4 c0 = *(const float4*)&C[ebase];
        float4 c1 = *(const float4*)&C[ebase + 4];
        st4tf(&Es[er][ec], e0); st4tf(&Es[er][ec + 4], e1);
        st4tf(&Cs[er][ec], c0); st4tf(&Cs[er][ec + 4], c1);
        __syncthreads();
        #pragma unroll
        for (int s = 0; s < 2; ++s) {
            const int kk = s * 8;
            uint32_t af[2][4];
            #pragma unroll
            for (int mt = 0; mt < 2; ++mt) {
                const int m = wm * 32 + mt * 16 + g;
                af[mt][0] = As[m][kk + cc];
                af[mt][1] = As[m + 8][kk + cc];
                af[mt][2] = As[m][kk + cc + 4];
                af[mt][3] = As[m + 8][kk + cc + 4];
            }
            #pragma unroll
            for (int nt = 0; nt < 4; ++nt) {
                const int n = wn * 32 + nt * 8 + g;
                uint32_t bE[2], bC[2];
                bE[0] = Es[kk + cc][n]; bE[1] = Es[kk + cc + 4][n];
                bC[0] = Cs[kk + cc][n]; bC[1] = Cs[kk + cc + 4][n];
                #pragma unroll
                for (int mt = 0; mt < 2; ++mt) {
                    mma_tf32(accE[mt][nt], af[mt], bE);
                    mma_tf32(accC[mt][nt], af[mt], bC);
                }
            }
        }
        __syncthreads();
    }
    #pragma unroll
    for (int mt = 0; mt < 2; ++mt) {
        const int slot = wm * 32 + mt * 16 + g;
        #pragma unroll
        for (int nt = 0; nt < 4; ++nt) {
            const int col = col0 + wn * 32 + nt * 8 + 2 * cc;
            atomicAdd(&aggE[slot * 512 + col],           accE[mt][nt][0]);
            atomicAdd(&aggE[slot * 512 + col + 1],       accE[mt][nt][1]);
            atomicAdd(&aggE[(slot + 8) * 512 + col],     accE[mt][nt][2]);
            atomicAdd(&aggE[(slot + 8) * 512 + col + 1], accE[mt][nt][3]);
            atomicAdd(&aggC[slot * 512 + col],           accC[mt][nt][0]);
            atomicAdd(&aggC[slot * 512 + col + 1],       accC[mt][nt][1]);
            atomicAdd(&aggC[(slot + 8) * 512 + col],     accC[mt][nt][2]);
            atomicAdd(&aggC[(slot + 8) * 512 + col + 1], accC[mt][nt][3]);
        }
    }
}

__global__ void zero_kernel(float* p, int n) {
    int i = blockIdx.x * blockDim.x + threadIdx.x;
    if (i < n) p[i] = 0.f;
}

__global__ void final_state_kernel(const float* __restrict__ state,
                                   const float* __restrict__ er,
                                   const float* __restrict__ wr,
                                   float* __restrict__ out)
{
    int i = blockIdx.x * blockDim.x + threadIdx.x;
    float e = fminf(fmaxf(er[i], 0.f), 1.f);
    out[i] = state[i] * (1.f - e) + wr[i];
}

// ------------------------------- launch --------------------------------------
extern "C" void kernel_launch(void* const* d_in, const int* in_sizes, int n_in,
                              void* d_out, int out_size)
{
    const float* X     = (const float*)d_in[0];
    const float* state = (const float*)d_in[1];
    const float* Wq    = (const float*)d_in[2];
    const float* Wk    = (const float*)d_in[3];
    const float* Wv    = (const float*)d_in[4];
    const float* Wo    = (const float*)d_in[5];
    const float* gamma = (const float*)d_in[6];
    const float* beta  = (const float*)d_in[7];
    const float* Wa    = (const float*)d_in[8];
    const float* Wg    = (const float*)d_in[9];
    const float* bg    = (const float*)d_in[10];
    const float* We    = (const float*)d_in[11];
    const float* be    = (const float*)d_in[12];
    const float* Wc    = (const float*)d_in[13];
    const float* bc    = (const float*)d_in[14];
    float* out = (float*)d_out;

    float *pE, *pC, *pT, *pAttn, *pGate, *pWS;
    cudaGetSymbolAddress((void**)&pE, g_E);
    cudaGetSymbolAddress((void**)&pC, g_C);
    cudaGetSymbolAddress((void**)&pT, g_T);
    cudaGetSymbolAddress((void**)&pAttn, g_attn);
    cudaGetSymbolAddress((void**)&pGate, g_gate);
    cudaGetSymbolAddress((void**)&pWS, g_ws);
    float* pKp  = pWS + OFF_KP;
    float* pV   = pWS + OFF_V;
    float* pM1  = pWS + OFF_M1;
    float* pM2  = pWS + OFF_M2;
    float* pVWo = pWS + OFF_VWO;
    float* pAgg0 = pWS + OFF_AGG;
    float* pAgg1 = pWS + OFF_AGG + KSLOTS * SDIM;

    const float scale = 1.0f / sqrtf((float)SDIM);

    // zero all atomic-target buffers (deterministic per call)
    zero_kernel<<<WS_TOTAL / 512, 512>>>(pWS, WS_TOTAL);

    // Kp = state@Wk, V = state@Wv   (split-K x4)
    state_proj_kernel<<<dim3(8, 2, 4), 256>>>(state, Wk, Wv, pKp, pV);

    // M1 = Wq @ Kp^T [1024,64]; M2 = Wa @ state^T [1024,64]  (split-K x4)
    abt_kernel<<<dim3(16, 4), 256>>>(Wq, pKp, pM1);
    abt_kernel<<<dim3(16, 4), 256>>>(Wa, state, pM2);

    // VWo = V @ Wo [64,1024]  (split-K x4)
    smallab_kernel<<<dim3(16, 4), 256>>>(pV, Wo, pVWo, DDIM);

    // attn = softmax(X @ M1 * scale)   -- tf32 tensor cores
    attn1_tf32_kernel<<<512, 256>>>(X, pM1, pAttn, scale);

    // T = X + attn @ VWo
    sgemm128<1><<<dim3(8, 512), 256>>>(pAttn, KSLOTS, pVWo, DDIM, pT, DDIM,
                                       KSLOTS, X);

    // h = LN(T) -> out[0:N*D]; gate = sigmoid(h.Wg + bg)
    ln_gate_kernel<<<NROWS, 256>>>(pT, gamma, beta, Wg, bg, out, pGate);

    // weighted = gate * softmax(h @ M2)   -- fp32 (sharp logits)
    attn2_kernel<<<512, 256>>>(out, DDIM, DDIM, pM2, pAttn, 1.0f, pGate);

    // E = sigmoid(h@We+be), C = tanh(h@Wc+bc)  -- tf32 tensor cores
    tf32gemm<2><<<dim3(4, 512), 256>>>(out, We, pE, be);
    tf32gemm<3><<<dim3(4, 512), 256>>>(out, Wc, pC, bc);

    // erase_agg / write_agg fused  -- tf32 tensor cores
    agg2_tf32_kernel<<<dim3(4, 32), 256>>>(pAttn, pE, pC, pAgg0, pAgg1);

    // new_state -> out[N*D:]
    final_state_kernel<<<64, 512>>>(state, pAgg0, pAgg1,
                                    out + (size_t)NROWS * DDIM);
}

// round 11
// speedup vs baseline: 4.2332x; 1.0234x over previous
#include <cuda_runtime.h>
#include <math.h>
#include <stdint.h>

#define NROWS 65536
#define DDIM  1024
#define SDIM  512
#define KSLOTS 64

// ---------------- scratch (device globals; no allocation allowed) ------------
__device__ float g_E[NROWS * SDIM];       // erase_vec
__device__ float g_C[NROWS * SDIM];       // content
__device__ float g_T[NROWS * DDIM];       // x + read_out (pre-LN)
__device__ float g_attn[NROWS * KSLOTS];  // attn -> weighted (reused)
__device__ float g_gate[NROWS];           // write gate
// small atomic-target workspace: Kp | V | M1 | M2 | VWo | aggE | aggC
#define OFF_KP   0
#define OFF_V    32768
#define OFF_M1   65536
#define OFF_M2   131072
#define OFF_VWO  196608
#define OFF_AGG  262144
#define WS_TOTAL 327680
__device__ float g_ws[WS_TOTAL];

// ---------------- tf32 helpers ----------------------------------------------
__device__ __forceinline__ uint32_t f2tf(float x) {
    uint32_t t; asm("cvt.rna.tf32.f32 %0, %1;" : "=r"(t) : "f"(x)); return t;
}
__device__ __forceinline__ void st4tf(uint32_t* p, float4 v) {
    p[0] = f2tf(v.x); p[1] = f2tf(v.y); p[2] = f2tf(v.z); p[3] = f2tf(v.w);
}
// split one float into tf32 hi + tf32 lo (residual)
__device__ __forceinline__ void splitf(float x, uint32_t& h, uint32_t& l) {
    h = f2tf(x);
    l = f2tf(x - __uint_as_float(h));
}
__device__ __forceinline__ void st4split(uint32_t* ph, uint32_t* pl, float4 v) {
    splitf(v.x, ph[0], pl[0]); splitf(v.y, ph[1], pl[1]);
    splitf(v.z, ph[2], pl[2]); splitf(v.w, ph[3], pl[3]);
}
__device__ __forceinline__ void mma_tf32(float* d, const uint32_t* a,
                                         const uint32_t* b) {
    asm volatile(
        "mma.sync.aligned.m16n8k8.row.col.f32.tf32.tf32.f32 "
        "{%0,%1,%2,%3}, {%4,%5,%6,%7}, {%8,%9}, {%0,%1,%2,%3};\n"
        : "+f"(d[0]), "+f"(d[1]), "+f"(d[2]), "+f"(d[3])
        : "r"(a[0]), "r"(a[1]), "r"(a[2]), "r"(a[3]), "r"(b[0]), "r"(b[1]));
}

__device__ __forceinline__ float fast_sigmoid(float v) {
    return 1.f / (1.f + __expf(-v));
}
__device__ __forceinline__ float fast_tanh(float v) {
    float e2 = __expf(2.f * v);
    return (e2 - 1.f) / (e2 + 1.f);
}

// ================= tf32 tensor-core GEMM: C = act(A[M,1024]@B[1024,512]+bias)
template<int OP>  // 2 = sigmoid(acc+bias), 3 = tanh(acc+bias)
__global__ __launch_bounds__(256, 2)
void tf32gemm(const float* __restrict__ A,
              const float* __restrict__ B,
              float* __restrict__ C,
              const float* __restrict__ bias)
{
    __shared__ uint32_t As[2][128][20];
    __shared__ uint32_t Bs[2][16][136];
    const int tid = threadIdx.x;
    const int bx = blockIdx.x, by = blockIdx.y;
    const int lane = tid & 31;
    const int w = tid >> 5;
    const int wm = w & 1, wn = w >> 1;
    const int g = lane >> 2, cc = lane & 3;

    const int ar = tid >> 2, ac = (tid & 3) << 2;
    const int br = tid >> 5, bc = (tid & 31) << 2;

    const float* Ag = A + (size_t)(by * 128 + ar) * 1024 + ac;
    const float* Bg = B + (size_t)br * 512 + bx * 128 + bc;

    float acc[4][4][4];
    #pragma unroll
    for (int i = 0; i < 4; ++i)
        #pragma unroll
        for (int j = 0; j < 4; ++j)
            #pragma unroll
            for (int r = 0; r < 4; ++r) acc[i][j][r] = 0.f;

    float4 a0v = *(const float4*)Ag;
    float4 a1v = *(const float4*)(Ag + (size_t)64 * 1024);
    float4 b0v = *(const float4*)Bg;
    float4 b1v = *(const float4*)(Bg + (size_t)8 * 512);
    st4tf(&As[0][ar][ac], a0v);
    st4tf(&As[0][ar + 64][ac], a1v);
    st4tf(&Bs[0][br][bc], b0v);
    st4tf(&Bs[0][br + 8][bc], b1v);
    __syncthreads();

    int buf = 0;
    for (int kt = 0; kt < 64; ++kt) {
        if (kt < 63) {
            a0v = *(const float4*)(Ag + (kt + 1) * 16);
            a1v = *(const float4*)(Ag + (kt + 1) * 16 + (size_t)64 * 1024);
            b0v = *(const float4*)(Bg + (size_t)(kt + 1) * 16 * 512);
            b1v = *(const float4*)(Bg + (size_t)((kt + 1) * 16 + 8) * 512);
        }
        #pragma unroll
        for (int s = 0; s < 2; ++s) {
            const int kk = s * 8;
            uint32_t af[4][4], bf[4][2];
            #pragma unroll
            for (int i = 0; i < 4; ++i) {
                const int m = wm * 64 + i * 16 + g;
                af[i][0] = As[buf][m][kk + cc];
                af[i][1] = As[buf][m + 8][kk + cc];
                af[i][2] = As[buf][m][kk + cc + 4];
                af[i][3] = As[buf][m + 8][kk + cc + 4];
            }
            #pragma unroll
            for (int j = 0; j < 4; ++j) {
                const int n = wn * 32 + j * 8 + g;
                bf[j][0] = Bs[buf][kk + cc][n];
                bf[j][1] = Bs[buf][kk + cc + 4][n];
            }
            #pragma unroll
            for (int i = 0; i < 4; ++i)
                #pragma unroll
                for (int j = 0; j < 4; ++j)
                    mma_tf32(acc[i][j], af[i], bf[j]);
        }
        if (kt < 63) {
            buf ^= 1;
            st4tf(&As[buf][ar][ac], a0v);
            st4tf(&As[buf][ar + 64][ac], a1v);
            st4tf(&Bs[buf][br][bc], b0v);
            st4tf(&Bs[buf][br + 8][bc], b1v);
            __syncthreads();
        }
    }

    #pragma unroll
    for (int i = 0; i < 4; ++i) {
        const int row = by * 128 + wm * 64 + i * 16 + g;
        #pragma unroll
        for (int j = 0; j < 4; ++j) {
            const int col = bx * 128 + wn * 32 + j * 8 + 2 * cc;
            const float bb0 = bias[col], bb1 = bias[col + 1];
            float v0 = acc[i][j][0] + bb0, v1 = acc[i][j][1] + bb1;
            float v2 = acc[i][j][2] + bb0, v3 = acc[i][j][3] + bb1;
            if (OP == 2) {
                v0 = fast_sigmoid(v0); v1 = fast_sigmoid(v1);
                v2 = fast_sigmoid(v2); v3 = fast_sigmoid(v3);
            } else {
                v0 = fast_tanh(v0); v1 = fast_tanh(v1);
                v2 = fast_tanh(v2); v3 = fast_tanh(v3);
            }
            float2 p0; p0.x = v0; p0.y = v1;
            float2 p1; p1.x = v2; p1.y = v3;
            *(float2*)&C[(size_t)row * 512 + col] = p0;
            *(float2*)&C[(size_t)(row + 8) * 512 + col] = p1;
        }
    }
}

// ====== attn #1 (read): tf32 GEMM [128x64, K=1024] + register softmax ========
__global__ __launch_bounds__(256, 2)
void attn1_tf32_kernel(const float* __restrict__ A,   // [N,1024]
                       const float* __restrict__ Bm,  // [1024,64]
                       float* __restrict__ out,       // [N,64]
                       float scale)
{
    __shared__ uint32_t As[2][128][20];
    __shared__ uint32_t Bs[2][16][72];
    const int tid = threadIdx.x;
    const int lane = tid & 31, w = tid >> 5;
    const int g = lane >> 2, cc = lane & 3;
    const int m0 = w << 4;
    const int row0 = blockIdx.x * 128;

    const int ar = tid >> 1, ak = (tid & 1) << 3;
    const int br = tid >> 4, bn = (tid & 15) << 2;
    const float* Ag = A + (size_t)(row0 + ar) * 1024 + ak;
    const float* Bg = Bm + (size_t)br * 64 + bn;

    float acc[8][4];
    #pragma unroll
    for (int i = 0; i < 8; ++i)
        #pragma unroll
        for (int j = 0; j < 4; ++j) acc[i][j] = 0.f;

    float4 a0 = *(const float4*)Ag;
    float4 a1 = *(const float4*)(Ag + 4);
    float4 bv = *(const float4*)Bg;
    st4tf(&As[0][ar][ak], a0);
    st4tf(&As[0][ar][ak + 4], a1);
    st4tf(&Bs[0][br][bn], bv);
    __syncthreads();

    int buf = 0;
    for (int kt = 0; kt < 64; ++kt) {
        if (kt < 63) {
            a0 = *(const float4*)(Ag + (kt + 1) * 16);
            a1 = *(const float4*)(Ag + (kt + 1) * 16 + 4);
            bv = *(const float4*)(Bg + (size_t)(kt + 1) * 16 * 64);
        }
        #pragma unroll
        for (int s = 0; s < 2; ++s) {
            const int kk = s * 8;
            uint32_t af[4];
            af[0] = As[buf][m0 + g][kk + cc];
            af[1] = As[buf][m0 + g + 8][kk + cc];
            af[2] = As[buf][m0 + g][kk + cc + 4];
            af[3] = As[buf][m0 + g + 8][kk + cc + 4];
            #pragma unroll
            for (int nt = 0; nt < 8; ++nt) {
                uint32_t bf[2];
                bf[0] = Bs[buf][kk + cc][nt * 8 + g];
                bf[1] = Bs[buf][kk + cc + 4][nt * 8 + g];
                mma_tf32(acc[nt], af, bf);
            }
        }
        if (kt < 63) {
            buf ^= 1;
            st4tf(&As[buf][ar][ak], a0);
            st4tf(&As[buf][ar][ak + 4], a1);
            st4tf(&Bs[buf][br][bn], bv);
            __syncthreads();
        }
    }

    float mx0 = -1e30f, mx1 = -1e30f;
    #pragma unroll
    for (int nt = 0; nt < 8; ++nt) {
        mx0 = fmaxf(mx0, fmaxf(acc[nt][0], acc[nt][1]));
        mx1 = fmaxf(mx1, fmaxf(acc[nt][2], acc[nt][3]));
    }
    #pragma unroll
    for (int s2 = 1; s2 <= 2; s2 <<= 1) {
        mx0 = fmaxf(mx0, __shfl_xor_sync(0xffffffffu, mx0, s2));
        mx1 = fmaxf(mx1, __shfl_xor_sync(0xffffffffu, mx1, s2));
    }
    mx0 *= scale; mx1 *= scale;
    float s0 = 0.f, s1 = 0.f;
    #pragma unroll
    for (int nt = 0; nt < 8; ++nt) {
        acc[nt][0] = __expf(acc[nt][0] * scale - mx0);
        acc[nt][1] = __expf(acc[nt][1] * scale - mx0);
        acc[nt][2] = __expf(acc[nt][2] * scale - mx1);
        acc[nt][3] = __expf(acc[nt][3] * scale - mx1);
        s0 += acc[nt][0] + acc[nt][1];
        s1 += acc[nt][2] + acc[nt][3];
    }
    #pragma unroll
    for (int s2 = 1; s2 <= 2; s2 <<= 1) {
        s0 += __shfl_xor_sync(0xffffffffu, s0, s2);
        s1 += __shfl_xor_sync(0xffffffffu, s1, s2);
    }
    const float f0 = 1.f / s0, f1 = 1.f / s1;
    const int ra = row0 + m0 + g;
    #pragma unroll
    for (int nt = 0; nt < 8; ++nt) {
        const int col = nt * 8 + 2 * cc;
        float2 p0; p0.x = acc[nt][0] * f0; p0.y = acc[nt][1] * f0;
        float2 p1; p1.x = acc[nt][2] * f1; p1.y = acc[nt][3] * f1;
        *(float2*)&out[(size_t)ra * 64 + col] = p0;
        *(float2*)&out[(size_t)(ra + 8) * 64 + col] = p1;
    }
}

// ====== attn #2 (addr): split-tf32 (3-term, ~fp32 exact) + softmax + gate ====
__global__ __launch_bounds__(256, 2)
void attn2_tf32split_kernel(const float* __restrict__ A,   // [N,1024]
                            const float* __restrict__ Bm,  // [1024,64]
                            float* __restrict__ out,       // [N,64]
                            const float* __restrict__ gate)
{
    __shared__ uint32_t Ah[128][20], Al[128][20];
    __shared__ uint32_t Bh[16][72],  Bl[16][72];
    const int tid = threadIdx.x;
    const int lane = tid & 31, w = tid >> 5;
    const int g = lane >> 2, cc = lane & 3;
    const int m0 = w << 4;
    const int row0 = blockIdx.x * 128;

    const int ar = tid >> 1, ak = (tid & 1) << 3;
    const int br = tid >> 4, bn = (tid & 15) << 2;
    const float* Ag = A + (size_t)(row0 + ar) * 1024 + ak;
    const float* Bg = Bm + (size_t)br * 64 + bn;

    float acc[8][4];
    #pragma unroll
    for (int i = 0; i < 8; ++i)
        #pragma unroll
        for (int j = 0; j < 4; ++j) acc[i][j] = 0.f;

    float4 a0 = *(const float4*)Ag;
    float4 a1 = *(const float4*)(Ag + 4);
    float4 bv = *(const float4*)Bg;

    for (int kt = 0; kt < 64; ++kt) {
        st4split(&Ah[ar][ak], &Al[ar][ak], a0);
        st4split(&Ah[ar][ak + 4], &Al[ar][ak + 4], a1);
        st4split(&Bh[br][bn], &Bl[br][bn], bv);
        __syncthreads();
        if (kt < 63) {
            a0 = *(const float4*)(Ag + (kt + 1) * 16);
            a1 = *(const float4*)(Ag + (kt + 1) * 16 + 4);
            bv = *(const float4*)(Bg + (size_t)(kt + 1) * 16 * 64);
        }
        #pragma unroll
        for (int s = 0; s < 2; ++s) {
            const int kk = s * 8;
            uint32_t afh[4], afl[4];
            afh[0] = Ah[m0 + g][kk + cc];
            afh[1] = Ah[m0 + g + 8][kk + cc];
            afh[2] = Ah[m0 + g][kk + cc + 4];
            afh[3] = Ah[m0 + g + 8][kk + cc + 4];
            afl[0] = Al[m0 + g][kk + cc];
            afl[1] = Al[m0 + g + 8][kk + cc];
            afl[2] = Al[m0 + g][kk + cc + 4];
            afl[3] = Al[m0 + g + 8][kk + cc + 4];
            #pragma unroll
            for (int nt = 0; nt < 8; ++nt) {
                uint32_t bfh[2], bfl[2];
                bfh[0] = Bh[kk + cc][nt * 8 + g];
                bfh[1] = Bh[kk + cc + 4][nt * 8 + g];
                bfl[0] = Bl[kk + cc][nt * 8 + g];
                bfl[1] = Bl[kk + cc + 4][nt * 8 + g];
                mma_tf32(acc[nt], afh, bfh);
                mma_tf32(acc[nt], afl, bfh);
                mma_tf32(acc[nt], afh, bfl);
            }
        }
        __syncthreads();
    }

    float mx0 = -1e30f, mx1 = -1e30f;
    #pragma unroll
    for (int nt = 0; nt < 8; ++nt) {
        mx0 = fmaxf(mx0, fmaxf(acc[nt][0], acc[nt][1]));
        mx1 = fmaxf(mx1, fmaxf(acc[nt][2], acc[nt][3]));
    }
    #pragma unroll
    for (int s2 = 1; s2 <= 2; s2 <<= 1) {
        mx0 = fmaxf(mx0, __shfl_xor_sync(0xffffffffu, mx0, s2));
        mx1 = fmaxf(mx1, __shfl_xor_sync(0xffffffffu, mx1, s2));
    }
    float s0 = 0.f, s1 = 0.f;
    #pragma unroll
    for (int nt = 0; nt < 8; ++nt) {
        acc[nt][0] = __expf(acc[nt][0] - mx0);
        acc[nt][1] = __expf(acc[nt][1] - mx0);
        acc[nt][2] = __expf(acc[nt][2] - mx1);
        acc[nt][3] = __expf(acc[nt][3] - mx1);
        s0 += acc[nt][0] + acc[nt][1];
        s1 += acc[nt][2] + acc[nt][3];
    }
    #pragma unroll
    for (int s2 = 1; s2 <= 2; s2 <<= 1) {
        s0 += __shfl_xor_sync(0xffffffffu, s0, s2);
        s1 += __shfl_xor_sync(0xffffffffu, s1, s2);
    }
    const int ra = row0 + m0 + g;
    const float f0 = gate[ra] / s0, f1 = gate[ra + 8] / s1;
    #pragma unroll
    for (int nt = 0; nt < 8; ++nt) {
        const int col = nt * 8 + 2 * cc;
        float2 p0; p0.x = acc[nt][0] * f0; p0.y = acc[nt][1] * f0;
        float2 p1; p1.x = acc[nt][2] * f1; p1.y = acc[nt][3] * f1;
        *(float2*)&out[(size_t)ra * 64 + col] = p0;
        *(float2*)&out[(size_t)(ra + 8) * 64 + col] = p1;
    }
}

// ---------------- generic 128x128x8 SGEMM (K=64 read GEMM, +residual) --------
template<int OP>
__global__ __launch_bounds__(256, 2)
void sgemm128(const float* __restrict__ A, int lda,
              const float* __restrict__ B, int ldb,
              float* __restrict__ C, int ldc,
              int Kdim,
              const float* __restrict__ X)
{
    __shared__ float As[2][8][128];
    __shared__ float Bs[2][8][128];
    const int tid = threadIdx.x;
    const int bx = blockIdx.x, by = blockIdx.y;
    const int tr = (tid >> 4) << 3;
    const int tc = (tid & 15) << 3;

    const int aRow = tid >> 1;
    const int aCol = (tid & 1) << 2;
    const int bRow = tid >> 5;
    const int bCol = (tid & 31) << 2;

    const float* Aptr = A + (size_t)(by * 128 + aRow) * lda + aCol;
    const float* Bptr = B + (size_t)bRow * ldb + bx * 128 + bCol;

    float acc[8][8];
    #pragma unroll
    for (int i = 0; i < 8; ++i)
        #pragma unroll
        for (int j = 0; j < 8; ++j) acc[i][j] = 0.f;

    float4 av = *(const float4*)Aptr;
    float4 bv = *(const float4*)Bptr;
    As[0][aCol + 0][aRow] = av.x; As[0][aCol + 1][aRow] = av.y;
    As[0][aCol + 2][aRow] = av.z; As[0][aCol + 3][aRow] = av.w;
    *(float4*)&Bs[0][bRow][bCol] = bv;
    __syncthreads();

    const int KT = Kdim >> 3;
    int buf = 0;
    for (int kt = 0; kt < KT; ++kt) {
        if (kt + 1 < KT) {
            av = *(const float4*)(Aptr + (kt + 1) * 8);
            bv = *(const float4*)(Bptr + (size_t)(kt + 1) * 8 * ldb);
        }
        #pragma unroll
        for (int kk = 0; kk < 8; ++kk) {
            float a0[8], b0[8];
            *(float4*)&a0[0] = *(const float4*)&As[buf][kk][tr];
            *(float4*)&a0[4] = *(const float4*)&As[buf][kk][tr + 4];
            *(float4*)&b0[0] = *(const float4*)&Bs[buf][kk][tc];
            *(float4*)&b0[4] = *(const float4*)&Bs[buf][kk][tc + 4];
            #pragma unroll
            for (int i = 0; i < 8; ++i)
                #pragma unroll
                for (int j = 0; j < 8; ++j)
                    acc[i][j] += a0[i] * b0[j];
        }
        if (kt + 1 < KT) {
            buf ^= 1;
            As[buf][aCol + 0][aRow] = av.x; As[buf][aCol + 1][aRow] = av.y;
            As[buf][aCol + 2][aRow] = av.z; As[buf][aCol + 3][aRow] = av.w;
            *(float4*)&Bs[buf][bRow][bCol] = bv;
            __syncthreads();
        }
    }

    const int row0 = by * 128 + tr;
    const int col0 = bx * 128 + tc;
    #pragma unroll
    for (int i = 0; i < 8; ++i) {
        size_t off = (size_t)(row0 + i) * ldc + col0;
        float outv[8];
        #pragma unroll
        for (int j = 0; j < 8; ++j) {
            float v = acc[i][j];
            if (OP == 1) v += X[off + j];
            outv[j] = v;
        }
        *(float4*)&C[off]     = *(float4*)&outv[0];
        *(float4*)&C[off + 4] = *(float4*)&outv[4];
    }
}

// -------- state projections (split-K x4, atomic): Kp=state@Wk, V=state@Wv ----
__global__ __launch_bounds__(256)
void state_proj_kernel(const float* __restrict__ state,
                       const float* __restrict__ Wk,
                       const float* __restrict__ Wv,
                       float* __restrict__ Kp, float* __restrict__ V)
{
    const float* B = (blockIdx.y == 0) ? Wk : Wv;
    float* C = (blockIdx.y == 0) ? Kp : V;
    const int bx = blockIdx.x;
    const int kz = blockIdx.z;
    __shared__ float As[16][64];
    __shared__ float Bs[16][64];
    const int tid = threadIdx.x;
    const int rb = (tid >> 4) << 2;
    const int cb = (tid & 15) << 2;
    float acc[4][4];
    #pragma unroll
    for (int i = 0; i < 4; ++i)
        #pragma unroll
        for (int j = 0; j < 4; ++j) acc[i][j] = 0.f;

    for (int kt = kz * 8; kt < kz * 8 + 8; ++kt) {
        const int k0 = kt * 16;
        {
            int r = tid >> 2, c4 = (tid & 3) << 2;
            float4 v = *(const float4*)&state[r * 512 + k0 + c4];
            As[c4 + 0][r] = v.x; As[c4 + 1][r] = v.y;
            As[c4 + 2][r] = v.z; As[c4 + 3][r] = v.w;
        }
        {
            int r = tid >> 4, c4 = (tid & 15) << 2;
            *(float4*)&Bs[r][c4] = *(const float4*)&B[(k0 + r) * 512 + bx * 64 + c4];
        }
        __syncthreads();
        #pragma unroll
        for (int kk = 0; kk < 16; ++kk) {
            float a[4], b[4];
            *(float4*)a = *(const float4*)&As[kk][rb];
            *(float4*)b = *(const float4*)&Bs[kk][cb];
            #pragma unroll
            for (int i = 0; i < 4; ++i)
                #pragma unroll
                for (int j = 0; j < 4; ++j) acc[i][j] += a[i] * b[j];
        }
        __syncthreads();
    }
    #pragma unroll
    for (int i = 0; i < 4; ++i)
        #pragma unroll
        for (int j = 0; j < 4; ++j)
            atomicAdd(&C[(rb + i) * 512 + bx * 64 + cb + j], acc[i][j]);
}

// ----- C[M,64] = A[M,512] @ B64[64,512]^T (split-K x4, atomic) ---------------
__global__ __launch_bounds__(256)
void abt_kernel(const float* __restrict__ A,
                const float* __restrict__ B,
                float* __restrict__ C)
{
    const int r0 = blockIdx.x * 64;
    const int kz = blockIdx.y;
    __shared__ float As[16][68];
    __shared__ float Bs[16][68];
    const int tid = threadIdx.x;
    const int rb = (tid >> 4) << 2;
    const int cb = (tid & 15) << 2;
    const int lr = tid >> 2, lc4 = (tid & 3) << 2;
    float acc[4][4];
    #pragma unroll
    for (int i = 0; i < 4; ++i)
        #pragma unroll
        for (int j = 0; j < 4; ++j) acc[i][j] = 0.f;

    for (int kt = kz * 8; kt < kz * 8 + 8; ++kt) {
        const int k0 = kt * 16;
        float4 va = *(const float4*)&A[(size_t)(r0 + lr) * 512 + k0 + lc4];
        float4 vb = *(const float4*)&B[(size_t)lr * 512 + k0 + lc4];
        As[lc4 + 0][lr] = va.x; As[lc4 + 1][lr] = va.y;
        As[lc4 + 2][lr] = va.z; As[lc4 + 3][lr] = va.w;
        Bs[lc4 + 0][lr] = vb.x; Bs[lc4 + 1][lr] = vb.y;
        Bs[lc4 + 2][lr] = vb.z; Bs[lc4 + 3][lr] = vb.w;
        __syncthreads();
        #pragma unroll
        for (int kk = 0; kk < 16; ++kk) {
            float a[4], b[4];
            *(float4*)a = *(const float4*)&As[kk][rb];
            *(float4*)b = *(const float4*)&Bs[kk][cb];
            #pragma unroll
            for (int i = 0; i < 4; ++i)
                #pragma unroll
                for (int j = 0; j < 4; ++j) acc[i][j] += a[i] * b[j];
        }
        __syncthreads();
    }
    #pragma unroll
    for (int i = 0; i < 4; ++i)
        #pragma unroll
        for (int j = 0; j < 4; ++j)
            atomicAdd(&C[(size_t)(r0 + rb + i) * 64 + cb + j], acc[i][j]);
}

// ----- C[64,NC] = A[64,512] @ B[512,NC] (split-K x4, atomic; VWo builder) ----
__global__ __launch_bounds__(256)
void smallab_kernel(const float* __restrict__ A,
                    const float* __restrict__ B,
                    float* __restrict__ C, int NC)
{
    const int n0 = blockIdx.x * 64;
    const int kz = blockIdx.y;
    __shared__ float As[16][68];
    __shared__ float Bs[16][68];
    const int tid = threadIdx.x;
    const int rb = (tid >> 4) << 2;
    const int cb = (tid & 15) << 2;
    const int lr = tid >> 2, lc4 = (tid & 3) << 2;
    const int br = tid >> 4, bc4 = (tid & 15) << 2;
    float acc[4][4];
    #pragma unroll
    for (int i = 0; i < 4; ++i)
        #pragma unroll
        for (int j = 0; j < 4; ++j) acc[i][j] = 0.f;

    for (int kt = kz * 8; kt < kz * 8 + 8; ++kt) {
        const int k0 = kt * 16;
        float4 va = *(const float4*)&A[(size_t)lr * 512 + k0 + lc4];
        As[lc4 + 0][lr] = va.x; As[lc4 + 1][lr] = va.y;
        As[lc4 + 2][lr] = va.z; As[lc4 + 3][lr] = va.w;
        *(float4*)&Bs[br][bc4] =
            *(const float4*)&B[(size_t)(k0 + br) * NC + n0 + bc4];
        __syncthreads();
        #pragma unroll
        for (int kk = 0; kk < 16; ++kk) {
            float a[4], b[4];
            *(float4*)a = *(const float4*)&As[kk][rb];
            *(float4*)b = *(const float4*)&Bs[kk][cb];
            #pragma unroll
            for (int i = 0; i < 4; ++i)
                #pragma unroll
                for (int j = 0; j < 4; ++j) acc[i][j] += a[i] * b[j];
        }
        __syncthreads();
    }
    #pragma unroll
    for (int i = 0; i < 4; ++i)
        #pragma unroll
        for (int j = 0; j < 4; ++j)
            atomicAdd(&C[(size_t)(rb + i) * NC + n0 + cb + j], acc[i][j]);
}

// ---------------- layernorm (row 1024) fused with write-gate dot -------------
__global__ __launch_bounds__(256)
void ln_gate_kernel(const float* __restrict__ T,
                    const float* __restrict__ gamma,
                    const float* __restrict__ beta,
                    const float* __restrict__ Wg,
                    const float* __restrict__ bgp,
                    float* __restrict__ H,
                    float* __restrict__ gate)
{
    __shared__ float sm[8], sm2[8];
    __shared__ float s_mu, s_inv;
    const int row = blockIdx.x;
    const int t = threadIdx.x;
    const size_t base = (size_t)row * 1024 + t * 4;
    float4 v = *(const float4*)&T[base];
    float s  = v.x + v.y + v.z + v.w;
    float sq = v.x * v.x + v.y * v.y + v.z * v.z + v.w * v.w;
    #pragma unroll
    for (int o = 16; o > 0; o >>= 1) {
        s  += __shfl_down_sync(0xffffffffu, s, o);
        sq += __shfl_down_sync(0xffffffffu, sq, o);
    }
    const int lane = t & 31, w = t >> 5;
    if (lane == 0) { sm[w] = s; sm2[w] = sq; }
    __syncthreads();
    if (t == 0) {
        float S = 0.f, Q = 0.f;
        #pragma unroll
        for (int i = 0; i < 8; ++i) { S += sm[i]; Q += sm2[i]; }
        float mu = S * (1.f / 1024.f);
        float var = Q * (1.f / 1024.f) - mu * mu;
        s_mu = mu; s_inv = rsqrtf(var + 1e-6f);
    }
    __syncthreads();
    const float mu = s_mu, inv = s_inv;
    float4 g4 = *(const float4*)&gamma[t * 4];
    float4 b4 = *(const float4*)&beta[t * 4];
    float4 h;
    h.x = (v.x - mu) * inv * g4.x + b4.x;
    h.y = (v.y - mu) * inv * g4.y + b4.y;
    h.z = (v.z - mu) * inv * g4.z + b4.z;
    h.w = (v.w - mu) * inv * g4.w + b4.w;
    *(float4*)&H[base] = h;
    float4 wg = *(const float4*)&Wg[t * 4];
    float gd = h.x * wg.x + h.y * wg.y + h.z * wg.z + h.w * wg.w;
    #pragma unroll
    for (int o = 16; o > 0; o >>= 1) gd += __shfl_down_sync(0xffffffffu, gd, o);
    __syncthreads();
    if (lane == 0) sm[w] = gd;
    __syncthreads();
    if (t == 0) {
        float G = 0.f;
        #pragma unroll
        for (int i = 0; i < 8; ++i) G += sm[i];
        gate[row] = 1.f / (1.f + __expf(-(G + bgp[0])));
    }
}

// ====== fused tf32 aggregation: aggE += W^T@E, aggC += W^T@C (split-K) =======
__global__ __launch_bounds__(256, 2)
void agg2_tf32_kernel(const float* __restrict__ Wt,  // weighted [N,64]
                      const float* __restrict__ E,   // [N,512]
                      const float* __restrict__ C,   // [N,512]
                      float* __restrict__ aggE,
                      float* __restrict__ aggC)
{
    __shared__ uint32_t As[64][20];
    __shared__ uint32_t Es[16][136];
    __shared__ uint32_t Cs[16][136];
    const int tid = threadIdx.x;
    const int lane = tid & 31, w = tid >> 5;
    const int g = lane >> 2, cc = lane & 3;
    const int wm = w & 1, wn = w >> 1;
    const int col0 = blockIdx.x * 128;
    const int r0 = blockIdx.y * 1024;

    const int wrow = tid & 15;
    const int wslot = (tid >> 4) << 2;
    const int er = tid >> 4;
    const int ec = (tid & 15) << 3;

    float accE[2][4][4], accC[2][4][4];
    #pragma unroll
    for (int i = 0; i < 2; ++i)
        #pragma unroll
        for (int j = 0; j < 4; ++j)
            #pragma unroll
            for (int r = 0; r < 4; ++r) { accE[i][j][r] = 0.f; accC[i][j][r] = 0.f; }

    for (int it = 0; it < 64; ++it) {
        const int rr = r0 + it * 16;
        float4 wv = *(const float4*)&Wt[(size_t)(rr + wrow) * 64 + wslot];
        As[wslot + 0][wrow] = f2tf(wv.x);
        As[wslot + 1][wrow] = f2tf(wv.y);
        As[wslot + 2][wrow] = f2tf(wv.z);
        As[wslot + 3][wrow] = f2tf(wv.w);
        const size_t ebase = (size_t)(rr + er) * 512 + col0 + ec;
        float4 e0 = *(const float4*)&E[ebase];
        float4 e1 = *(const float4*)&E[ebase + 4];
        float4 c0 = *(const float4*)&C[ebase];
        float4 c1 = *(const float4*)&C[ebase + 4];
        st4tf(&Es[er][ec], e0); st4tf(&Es[er][ec + 4], e1);
        st4tf(&Cs[er][ec], c0); st4tf(&Cs[er][ec + 4], c1);
        __syncthreads();
        #pragma unroll
        for (int s = 0; s < 2; ++s) {
            const int kk = s * 8;
            uint32_t af[2][4];
            #pragma unroll
            for (int mt = 0; mt < 2; ++mt) {
                const int m = wm * 32 + mt * 16 + g;
                af[mt][0] = As[m][kk + cc];
                af[mt][1] = As[m + 8][kk + cc];
                af[mt][2] = As[m][kk + cc + 4];
                af[mt][3] = As[m + 8][kk + cc + 4];
            }
            #pragma unroll
            for (int nt = 0; nt < 4; ++nt) {
                const int n = wn * 32 + nt * 8 + g;
                uint32_t bE[2], bC[2];
                bE[0] = Es[kk + cc][n]; bE[1] = Es[kk + cc + 4][n];
                bC[0] = Cs[kk + cc][n]; bC[1] = Cs[kk + cc + 4][n];
                #pragma unroll
                for (int mt = 0; mt < 2; ++mt) {
                    mma_tf32(accE[mt][nt], af[mt], bE);
                    mma_tf32(accC[mt][nt], af[mt], bC);
                }
            }
        }
        __syncthreads();
    }
    #pragma unroll
    for (int mt = 0; mt < 2; ++mt) {
        const int slot = wm * 32 + mt * 16 + g;
        #pragma unroll
        for (int nt = 0; nt < 4; ++nt) {
            const int col = col0 + wn * 32 + nt * 8 + 2 * cc;
            atomicAdd(&aggE[slot * 512 + col],           accE[mt][nt][0]);
            atomicAdd(&aggE[slot * 512 + col + 1],       accE[mt][nt][1]);
            atomicAdd(&aggE[(slot + 8) * 512 + col],     accE[mt][nt][2]);
            atomicAdd(&aggE[(slot + 8) * 512 + col + 1], accE[mt][nt][3]);
            atomicAdd(&aggC[slot * 512 + col],           accC[mt][nt][0]);
            atomicAdd(&aggC[slot * 512 + col + 1],       accC[mt][nt][1]);
            atomicAdd(&aggC[(slot + 8) * 512 + col],     accC[mt][nt][2]);
            atomicAdd(&aggC[(slot + 8) * 512 + col + 1], accC[mt][nt][3]);
        }
    }
}

__global__ void zero_kernel(float* p, int n) {
    int i = blockIdx.x * blockDim.x + threadIdx.x;
    if (i < n) p[i] = 0.f;
}

__global__ void final_state_kernel(const float* __restrict__ state,
                                   const float* __restrict__ er,
                                   const float* __restrict__ wr,
                                   float* __restrict__ out)
{
    int i = blockIdx.x * blockDim.x + threadIdx.x;
    float e = fminf(fmaxf(er[i], 0.f), 1.f);
    out[i] = state[i] * (1.f - e) + wr[i];
}

// ------------------------------- launch --------------------------------------
extern "C" void kernel_launch(void* const* d_in, const int* in_sizes, int n_in,
                              void* d_out, int out_size)
{
    const float* X     = (const float*)d_in[0];
    const float* state = (const float*)d_in[1];
    const float* Wq    = (const float*)d_in[2];
    const float* Wk    = (const float*)d_in[3];
    const float* Wv    = (const float*)d_in[4];
    const float* Wo    = (const float*)d_in[5];
    const float* gamma = (const float*)d_in[6];
    const float* beta  = (const float*)d_in[7];
    const float* Wa    = (const float*)d_in[8];
    const float* Wg    = (const float*)d_in[9];
    const float* bg    = (const float*)d_in[10];
    const float* We    = (const float*)d_in[11];
    const float* be    = (const float*)d_in[12];
    const float* Wc    = (const float*)d_in[13];
    const float* bc    = (const float*)d_in[14];
    float* out = (float*)d_out;

    float *pE, *pC, *pT, *pAttn, *pGate, *pWS;
    cudaGetSymbolAddress((void**)&pE, g_E);
    cudaGetSymbolAddress((void**)&pC, g_C);
    cudaGetSymbolAddress((void**)&pT, g_T);
    cudaGetSymbolAddress((void**)&pAttn, g_attn);
    cudaGetSymbolAddress((void**)&pGate, g_gate);
    cudaGetSymbolAddress((void**)&pWS, g_ws);
    float* pKp  = pWS + OFF_KP;
    float* pV   = pWS + OFF_V;
    float* pM1  = pWS + OFF_M1;
    float* pM2  = pWS + OFF_M2;
    float* pVWo = pWS + OFF_VWO;
    float* pAgg0 = pWS + OFF_AGG;
    float* pAgg1 = pWS + OFF_AGG + KSLOTS * SDIM;

    const float scale = 1.0f / sqrtf((float)SDIM);

    // zero all atomic-target buffers (deterministic per call)
    zero_kernel<<<WS_TOTAL / 512, 512>>>(pWS, WS_TOTAL);

    // Kp = state@Wk, V = state@Wv   (split-K x4)
    state_proj_kernel<<<dim3(8, 2, 4), 256>>>(state, Wk, Wv, pKp, pV);

    // M1 = Wq @ Kp^T [1024,64]; M2 = Wa @ state^T [1024,64]  (split-K x4)
    abt_kernel<<<dim3(16, 4), 256>>>(Wq, pKp, pM1);
    abt_kernel<<<dim3(16, 4), 256>>>(Wa, state, pM2);

    // VWo = V @ Wo [64,1024]  (split-K x4)
    smallab_kernel<<<dim3(16, 4), 256>>>(pV, Wo, pVWo, DDIM);

    // attn = softmax(X @ M1 * scale)   -- tf32 tensor cores
    attn1_tf32_kernel<<<512, 256>>>(X, pM1, pAttn, scale);

    // T = X + attn @ VWo
    sgemm128<1><<<dim3(8, 512), 256>>>(pAttn, KSLOTS, pVWo, DDIM, pT, DDIM,
                                       KSLOTS, X);

    // h = LN(T) -> out[0:N*D]; gate = sigmoid(h.Wg + bg)
    ln_gate_kernel<<<NROWS, 256>>>(pT, gamma, beta, Wg, bg, out, pGate);

    // weighted = gate * softmax(h @ M2)   -- split-tf32 (fp32-accurate)
    attn2_tf32split_kernel<<<512, 256>>>(out, pM2, pAttn, pGate);

    // E = sigmoid(h@We+be), C = tanh(h@Wc+bc)  -- tf32 tensor cores
    tf32gemm<2><<<dim3(4, 512), 256>>>(out, We, pE, be);
    tf32gemm<3><<<dim3(4, 512), 256>>>(out, Wc, pC, bc);

    // erase_agg / write_agg fused  -- tf32 tensor cores (split-K x64)
    agg2_tf32_kernel<<<dim3(4, 64), 256>>>(pAttn, pE, pC, pAgg0, pAgg1);

    // new_state -> out[N*D:]
    final_state_kernel<<<64, 512>>>(state, pAgg0, pAgg1,
                                    out + (size_t)NROWS * DDIM);
}